// round 8
// baseline (speedup 1.0000x reference)
#include <cuda_runtime.h>
#include <cstdint>

#define NNODES 100000
#define MAXE   1000000

// ---------------- scratch (static __device__ globals; no allocation) -------
__device__ __align__(16) float4 g_bufA[NNODES * 32];   // 100000 x 128 floats
__device__ __align__(16) float4 g_bufB[NNODES * 32];   // 100000 x 128 floats
__device__ __align__(16) float4 g_hw3 [NNODES * 10];   // 100000 x 40 floats
__device__ float g_dinv[NNODES];
__device__ int   g_icnt[NNODES];
__device__ int   g_fc  [NNODES];
__device__ int   g_rs  [NNODES + 1];
__device__ int   g_perm[MAXE];
__device__ int   g_bsum[512];
__device__ int   g_boff[512];
__device__ float g_sums[512];
__device__ __align__(16) float g_scale[256];
__device__ __align__(16) float g_shift[256];
__device__ unsigned g_keys[4];

#define SCAN_BLOCKS 391

// ---------------- threefry2x32 (JAX-exact, 20 rounds) ----------------------
__device__ __forceinline__ void tf_round(uint32_t &x0, uint32_t &x1, int r) {
    x0 += x1;
    x1 = __funnelshift_l(x1, x1, r);
    x1 ^= x0;
}

__device__ __forceinline__ uint2 tf_full(uint32_t k0, uint32_t k1, uint32_t x0, uint32_t x1) {
    uint32_t k2 = k0 ^ k1 ^ 0x1BD11BDAu;
    x0 += k0; x1 += k1;
    tf_round(x0,x1,13); tf_round(x0,x1,15); tf_round(x0,x1,26); tf_round(x0,x1,6);
    x0 += k1; x1 += k2 + 1u;
    tf_round(x0,x1,17); tf_round(x0,x1,29); tf_round(x0,x1,16); tf_round(x0,x1,24);
    x0 += k2; x1 += k0 + 2u;
    tf_round(x0,x1,13); tf_round(x0,x1,15); tf_round(x0,x1,26); tf_round(x0,x1,6);
    x0 += k0; x1 += k1 + 3u;
    tf_round(x0,x1,17); tf_round(x0,x1,29); tf_round(x0,x1,16); tf_round(x0,x1,24);
    x0 += k1; x1 += k2 + 4u;
    tf_round(x0,x1,13); tf_round(x0,x1,15); tf_round(x0,x1,26); tf_round(x0,x1,6);
    x0 += k2; x1 += k0 + 5u;
    return make_uint2(x0, x1);
}

__device__ __forceinline__ uint32_t tf_bits_xor(uint32_t k0, uint32_t k1, uint32_t k2, uint32_t ctr) {
    uint32_t x0 = k0;
    uint32_t x1 = ctr + k1;
    tf_round(x0,x1,13); tf_round(x0,x1,15); tf_round(x0,x1,26); tf_round(x0,x1,6);
    x0 += k1; x1 += k2 + 1u;
    tf_round(x0,x1,17); tf_round(x0,x1,29); tf_round(x0,x1,16); tf_round(x0,x1,24);
    x0 += k2; x1 += k0 + 2u;
    tf_round(x0,x1,13); tf_round(x0,x1,15); tf_round(x0,x1,26); tf_round(x0,x1,6);
    x0 += k0; x1 += k1 + 3u;
    tf_round(x0,x1,17); tf_round(x0,x1,29); tf_round(x0,x1,16); tf_round(x0,x1,24);
    x0 += k1; x1 += k2 + 4u;
    tf_round(x0,x1,13); tf_round(x0,x1,15); tf_round(x0,x1,26); tf_round(x0,x1,6);
    x0 += k2; x1 += k0 + 5u;
    return x0 ^ x1;
}

__global__ void k_keys() {
    if (threadIdx.x == 0) {
        uint2 a = tf_full(0u, 42u, 0u, 0u);
        uint2 b = tf_full(0u, 42u, 0u, 1u);
        g_keys[0] = a.x; g_keys[1] = a.y;
        g_keys[2] = b.x; g_keys[3] = b.y;
    }
}

// ---------------- graph preprocessing --------------------------------------
__global__ void k_zero() {
    int i = blockIdx.x * 256 + threadIdx.x;
    if (i < NNODES) { g_icnt[i] = 0; g_fc[i] = 0; }
    if (i < 512)    g_sums[i] = 0.f;
}

__global__ void k_degree(const int* __restrict__ dst, int E) {
    int e = blockIdx.x * 256 + threadIdx.x;
    if (e < E) atomicAdd(&g_icnt[dst[e]], 1);
}

__global__ void k_dinv() {
    int i = blockIdx.x * 256 + threadIdx.x;
    if (i < NNODES) g_dinv[i] = rsqrtf((float)g_icnt[i] + 1.0f);
}

__global__ __launch_bounds__(256) void k_scan_local() {
    __shared__ int s[256];
    int t = threadIdx.x;
    int i = blockIdx.x * 256 + t;
    int v = (i < NNODES) ? g_icnt[i] : 0;
    s[t] = v;
    __syncthreads();
#pragma unroll
    for (int off = 1; off < 256; off <<= 1) {
        int add = (t >= off) ? s[t - off] : 0;
        __syncthreads();
        s[t] += add;
        __syncthreads();
    }
    if (i < NNODES) g_rs[i] = s[t] - v;
    if (t == 255) g_bsum[blockIdx.x] = s[255];
}

__global__ __launch_bounds__(512) void k_scan_block() {
    __shared__ int s[512];
    int t = threadIdx.x;
    int v = (t < SCAN_BLOCKS) ? g_bsum[t] : 0;
    s[t] = v;
    __syncthreads();
#pragma unroll
    for (int off = 1; off < 512; off <<= 1) {
        int add = (t >= off) ? s[t - off] : 0;
        __syncthreads();
        s[t] += add;
        __syncthreads();
    }
    g_boff[t] = s[t] - v;
}

__global__ void k_scan_add(int E) {
    int i = blockIdx.x * 256 + threadIdx.x;
    if (i < NNODES) g_rs[i] += g_boff[blockIdx.x];
    if (i == NNODES) g_rs[NNODES] = E;
}

__global__ void k_fill(const int* __restrict__ src, const int* __restrict__ dst, int E) {
    int e = blockIdx.x * 256 + threadIdx.x;
    if (e >= E) return;
    int d = dst[e];
    int pos = g_rs[d] + atomicAdd(&g_fc[d], 1);
    g_perm[pos] = src[e];
}

// ---------------- TF32 split-MMA GEMM, B resident + A double-buffered ------
// 3xTF32: a=ahi+alo, b=bhi+blo; D += ahi*bhi + alo*bhi + ahi*blo (err ~2^-22)
// 512 threads, tile 256 x NCPAD, 16 warps as 8m x 2n (warp: 32 rows x NCPAD/2).
// B (128 x NC weights) staged ONCE packed hi/lo; A double-buffered 16-k chunks
// with register prefetch; ONE __syncthreads per chunk.
__device__ __forceinline__ uint32_t f2tf32(float x) {
    uint32_t r;
    asm("cvt.rna.tf32.f32 %0, %1;" : "=r"(r) : "f"(x));
    return r;
}
__device__ __forceinline__ float f2tf32f(float x) {
    return __uint_as_float(f2tf32(x));
}

#define MMA_TF32(cc, a0,a1,a2,a3, b0,b1)                                       \
    asm volatile("mma.sync.aligned.m16n8k8.row.col.f32.tf32.tf32.f32 "         \
                 "{%0,%1,%2,%3}, {%4,%5,%6,%7}, {%8,%9}, {%0,%1,%2,%3};"       \
                 : "+f"(cc[0]), "+f"(cc[1]), "+f"(cc[2]), "+f"(cc[3])          \
                 : "r"(a0), "r"(a1), "r"(a2), "r"(a3), "r"(b0), "r"(b1))

template<int NCPAD>
__global__ __launch_bounds__(512) void sgemm_tf32b(
    const float* __restrict__ A, const float* __restrict__ B,
    float* __restrict__ C, int M, int NC)
{
    constexpr int NT = NCPAD / 16;             // n-tiles of 8 per warp
    extern __shared__ float4 sm4[];
    float4* Bp = sm4;                          // [16][4][NCPAD+2]
    float4* Ap = sm4 + 16 * 4 * (NCPAD + 2);   // [2][2][4][258]

    int tid  = threadIdx.x;
    int warp = tid >> 5, lane = tid & 31;
    int wm = warp >> 1, wn = warp & 1;
    int gid = lane >> 2, ctid = lane & 3;
    int row0 = blockIdx.x * 256;
    int wr = wm * 32;
    int wc = wn * (NCPAD / 2);

    float c[2][NT][4];
#pragma unroll
    for (int mt = 0; mt < 2; mt++)
#pragma unroll
        for (int nt = 0; nt < NT; nt++)
#pragma unroll
            for (int j = 0; j < 4; j++) c[mt][nt][j] = 0.f;

    // ---- stage full B (hi/lo packed) ----
    for (int idx = tid; idx < 64 * NCPAD; idx += 512) {
        int cc = idx & (NCPAD - 1);
        int s  = idx / NCPAD;          // 0..63
        int g = s >> 2, t = s & 3;
        int k = g * 8 + t;
        float a0 = (cc < NC) ? B[k * NC + cc] : 0.f;
        float a1 = (cc < NC) ? B[(k + 4) * NC + cc] : 0.f;
        float h0 = f2tf32f(a0), h1 = f2tf32f(a1);
        Bp[(g * 4 + t) * (NCPAD + 2) + cc] =
            make_float4(h0, h1, f2tf32f(a0 - h0), f2tf32f(a1 - h1));
    }

    int ar = tid >> 1, ag = tid & 1;
    int gr = row0 + ar;
    const float* Arow = A + gr * 128 + ag * 8;

    // A split+store helper
    auto storeA = [&](int buf, float4 v0, float4 v1) {
        float vv[8] = {v0.x, v0.y, v0.z, v0.w, v1.x, v1.y, v1.z, v1.w};
        float h[8], l[8];
#pragma unroll
        for (int t = 0; t < 8; t++) {
            h[t] = f2tf32f(vv[t]);
            l[t] = f2tf32f(vv[t] - h[t]);
        }
#pragma unroll
        for (int t = 0; t < 4; t++)
            Ap[((buf * 2 + ag) * 4 + t) * 258 + ar] =
                make_float4(h[t], h[t + 4], l[t], l[t + 4]);
    };

    // ---- stage A chunk 0 -> buf 0 ----
    {
        float4 v0 = make_float4(0.f,0.f,0.f,0.f), v1 = v0;
        if (gr < M) { v0 = *(const float4*)(Arow); v1 = *(const float4*)(Arow + 4); }
        storeA(0, v0, v1);
    }
    __syncthreads();

    for (int it = 0; it < 8; it++) {
        int b = it & 1;
        float4 p0 = make_float4(0.f,0.f,0.f,0.f), p1 = p0;
        if (it < 7 && gr < M) {
            p0 = *(const float4*)(Arow + (it + 1) * 16);
            p1 = *(const float4*)(Arow + (it + 1) * 16 + 4);
        }
#pragma unroll
        for (int g = 0; g < 2; g++) {
            int G = it * 2 + g;
            const float4* Abase = Ap + ((b * 2 + g) * 4 + ctid) * 258;
            float4 alo0 = Abase[wr + gid];
            float4 ahi0 = Abase[wr + gid + 8];
            float4 alo1 = Abase[wr + 16 + gid];
            float4 ahi1 = Abase[wr + 16 + gid + 8];
            uint32_t ah0[4] = {__float_as_uint(alo0.x), __float_as_uint(ahi0.x),
                               __float_as_uint(alo0.y), __float_as_uint(ahi0.y)};
            uint32_t al0[4] = {__float_as_uint(alo0.z), __float_as_uint(ahi0.z),
                               __float_as_uint(alo0.w), __float_as_uint(ahi0.w)};
            uint32_t ah1[4] = {__float_as_uint(alo1.x), __float_as_uint(ahi1.x),
                               __float_as_uint(alo1.y), __float_as_uint(ahi1.y)};
            uint32_t al1[4] = {__float_as_uint(alo1.z), __float_as_uint(ahi1.z),
                               __float_as_uint(alo1.w), __float_as_uint(ahi1.w)};
            const float4* Bbase = Bp + (G * 4 + ctid) * (NCPAD + 2) + wc;
#pragma unroll
            for (int nt = 0; nt < NT; nt++) {
                float4 bb = Bbase[nt * 8 + gid];
                uint32_t bh0 = __float_as_uint(bb.x), bh1 = __float_as_uint(bb.y);
                uint32_t bl0 = __float_as_uint(bb.z), bl1 = __float_as_uint(bb.w);
                MMA_TF32(c[0][nt], ah0[0], ah0[1], ah0[2], ah0[3], bh0, bh1);
                MMA_TF32(c[0][nt], al0[0], al0[1], al0[2], al0[3], bh0, bh1);
                MMA_TF32(c[0][nt], ah0[0], ah0[1], ah0[2], ah0[3], bl0, bl1);
                MMA_TF32(c[1][nt], ah1[0], ah1[1], ah1[2], ah1[3], bh0, bh1);
                MMA_TF32(c[1][nt], al1[0], al1[1], al1[2], al1[3], bh0, bh1);
                MMA_TF32(c[1][nt], ah1[0], ah1[1], ah1[2], ah1[3], bl0, bl1);
            }
        }
        if (it < 7) {
            storeA(b ^ 1, p0, p1);
            __syncthreads();
        }
    }

#pragma unroll
    for (int mt = 0; mt < 2; mt++) {
        int r0 = row0 + wr + mt * 16 + gid;
        int r1 = r0 + 8;
#pragma unroll
        for (int nt = 0; nt < NT; nt++) {
            int ccol = wc + nt * 8 + ctid * 2;
            if (ccol < NC) {
                if (r0 < M) *(float2*)(C + r0 * NC + ccol) = make_float2(c[mt][nt][0], c[mt][nt][1]);
                if (r1 < M) *(float2*)(C + r1 * NC + ccol) = make_float2(c[mt][nt][2], c[mt][nt][3]);
            }
        }
    }
}

// ---------------- CSR SpMM + fused BN partial stats ------------------------
__global__ __launch_bounds__(256) void spmm128s(
    const float4* __restrict__ hw, float4* __restrict__ agg,
    const float* __restrict__ bias, float* __restrict__ sums)
{
    __shared__ float bsum[128], bsq[128];
    int tid = threadIdx.x;
    if (tid < 128) { bsum[tid] = 0.f; bsq[tid] = 0.f; }
    __syncthreads();

    int row = blockIdx.x * 8 + (tid >> 5);     // NNODES % 8 == 0: always valid
    int lane = tid & 31;
    int beg = __ldg(&g_rs[row]);
    int end = __ldg(&g_rs[row + 1]);
    float di = g_dinv[row];
    float di2 = di * di;

    float4 self = __ldg(hw + row * 32 + lane);
    float4 b = ((const float4*)bias)[lane];
    float4 acc  = make_float4(fmaf(self.x, di2, b.x), fmaf(self.y, di2, b.y),
                              fmaf(self.z, di2, b.z), fmaf(self.w, di2, b.w));
    float4 acc2 = make_float4(0.f, 0.f, 0.f, 0.f);

    int j = beg;
    for (; j + 1 < end; j += 2) {
        int s0 = __ldg(&g_perm[j]);
        int s1 = __ldg(&g_perm[j + 1]);
        float n0 = __ldg(&g_dinv[s0]) * di;
        float n1 = __ldg(&g_dinv[s1]) * di;
        float4 v0 = __ldg(hw + s0 * 32 + lane);
        float4 v1 = __ldg(hw + s1 * 32 + lane);
        acc.x  = fmaf(v0.x, n0, acc.x);  acc.y  = fmaf(v0.y, n0, acc.y);
        acc.z  = fmaf(v0.z, n0, acc.z);  acc.w  = fmaf(v0.w, n0, acc.w);
        acc2.x = fmaf(v1.x, n1, acc2.x); acc2.y = fmaf(v1.y, n1, acc2.y);
        acc2.z = fmaf(v1.z, n1, acc2.z); acc2.w = fmaf(v1.w, n1, acc2.w);
    }
    if (j < end) {
        int s0 = __ldg(&g_perm[j]);
        float n0 = __ldg(&g_dinv[s0]) * di;
        float4 v0 = __ldg(hw + s0 * 32 + lane);
        acc.x = fmaf(v0.x, n0, acc.x); acc.y = fmaf(v0.y, n0, acc.y);
        acc.z = fmaf(v0.z, n0, acc.z); acc.w = fmaf(v0.w, n0, acc.w);
    }
    float4 o = make_float4(acc.x + acc2.x, acc.y + acc2.y,
                           acc.z + acc2.z, acc.w + acc2.w);
    agg[row * 32 + lane] = o;

    int cch = lane * 4;
    atomicAdd(&bsum[cch + 0], o.x); atomicAdd(&bsum[cch + 1], o.y);
    atomicAdd(&bsum[cch + 2], o.z); atomicAdd(&bsum[cch + 3], o.w);
    atomicAdd(&bsq[cch + 0], o.x * o.x); atomicAdd(&bsq[cch + 1], o.y * o.y);
    atomicAdd(&bsq[cch + 2], o.z * o.z); atomicAdd(&bsq[cch + 3], o.w * o.w);
    __syncthreads();
    if (tid < 128) {
        atomicAdd(&sums[tid],       bsum[tid]);
        atomicAdd(&sums[128 + tid], bsq[tid]);
    }
}

// ---------------- fused SpMM(40) + log_softmax -----------------------------
__global__ __launch_bounds__(256) void spmm40ls(
    const float4* __restrict__ hw, float* __restrict__ out,
    const float* __restrict__ bias)
{
    int row = blockIdx.x * 8 + (threadIdx.x >> 5);
    int lane = threadIdx.x & 31;
    bool act = (lane < 10);
    int lc = act ? lane : 9;
    int beg = __ldg(&g_rs[row]);
    int end = __ldg(&g_rs[row + 1]);
    float di = g_dinv[row];
    float di2 = di * di;

    float4 self = __ldg(hw + row * 10 + lc);
    float4 b = ((const float4*)bias)[lc];
    float4 acc = make_float4(fmaf(self.x, di2, b.x), fmaf(self.y, di2, b.y),
                             fmaf(self.z, di2, b.z), fmaf(self.w, di2, b.w));
    for (int j = beg; j < end; j++) {
        int s = __ldg(&g_perm[j]);
        float n = __ldg(&g_dinv[s]) * di;
        float4 v = __ldg(hw + s * 10 + lc);
        acc.x = fmaf(v.x, n, acc.x); acc.y = fmaf(v.y, n, acc.y);
        acc.z = fmaf(v.z, n, acc.z); acc.w = fmaf(v.w, n, acc.w);
    }
    float mx = act ? fmaxf(fmaxf(acc.x, acc.y), fmaxf(acc.z, acc.w)) : -3.4e38f;
#pragma unroll
    for (int o = 16; o; o >>= 1) mx = fmaxf(mx, __shfl_xor_sync(0xffffffffu, mx, o));
    float s = act ? (expf(acc.x - mx) + expf(acc.y - mx) +
                     expf(acc.z - mx) + expf(acc.w - mx)) : 0.f;
#pragma unroll
    for (int o = 16; o; o >>= 1) s += __shfl_xor_sync(0xffffffffu, s, o);
    float l = mx + logf(s);
    if (act)
        ((float4*)out)[row * 10 + lane] =
            make_float4(acc.x - l, acc.y - l, acc.z - l, acc.w - l);
}

// ---------------- BN finalize ----------------------------------------------
__global__ void k_bnfinal(const float* __restrict__ sums,
                          const float* __restrict__ gamma, const float* __restrict__ beta,
                          float* __restrict__ sc, float* __restrict__ sh) {
    int c = threadIdx.x;
    const float inv_n = 1.0f / (float)NNODES;
    float mean = sums[c] * inv_n;
    float var  = sums[128 + c] * inv_n - mean * mean;
    var = fmaxf(var, 0.f);
    float rstd = rsqrtf(var + 1e-5f);
    float a = gamma[c] * rstd;
    sc[c] = a;
    sh[c] = beta[c] - mean * a;
}

// ---------------- fused BN + ReLU + exact threefry dropout -----------------
__global__ __launch_bounds__(256) void k_bndrop(
    const float4* __restrict__ in, float4* __restrict__ out,
    const float* __restrict__ sc, const float* __restrict__ sh,
    int layer, int n4)
{
    int t = blockIdx.x * 256 + threadIdx.x;
    if (t >= n4) return;
    uint32_t k0 = g_keys[layer * 2 + 0];
    uint32_t k1 = g_keys[layer * 2 + 1];
    uint32_t k2 = k0 ^ k1 ^ 0x1BD11BDAu;

    int c = (t & 31) * 4;
    float4 v = in[t];
    float4 a = *(const float4*)(sc + c);
    float4 b = *(const float4*)(sh + c);

    float r0 = fmaxf(fmaf(v.x, a.x, b.x), 0.f);
    float r1 = fmaxf(fmaf(v.y, a.y, b.y), 0.f);
    float r2 = fmaxf(fmaf(v.z, a.z, b.z), 0.f);
    float r3 = fmaxf(fmaf(v.w, a.w, b.w), 0.f);

    uint32_t i0 = (uint32_t)t * 4u;
    uint32_t m0 = tf_bits_xor(k0, k1, k2, i0 + 0u);
    uint32_t m1 = tf_bits_xor(k0, k1, k2, i0 + 1u);
    uint32_t m2 = tf_bits_xor(k0, k1, k2, i0 + 2u);
    uint32_t m3 = tf_bits_xor(k0, k1, k2, i0 + 3u);

    v.x = (m0 & 0x80000000u) ? 0.f : r0 + r0;
    v.y = (m1 & 0x80000000u) ? 0.f : r1 + r1;
    v.z = (m2 & 0x80000000u) ? 0.f : r2 + r2;
    v.w = (m3 & 0x80000000u) ? 0.f : r3 + r3;
    out[t] = v;
}

// ---------------- launch ---------------------------------------------------
extern "C" void kernel_launch(void* const* d_in, const int* in_sizes, int n_in,
                              void* d_out, int out_size) {
    const float* x   = (const float*)d_in[0];
    const int*   ei  = (const int*)  d_in[1];
    const float* W1  = (const float*)d_in[2];
    const float* b1  = (const float*)d_in[3];
    const float* g1  = (const float*)d_in[4];
    const float* be1 = (const float*)d_in[5];
    const float* W2  = (const float*)d_in[6];
    const float* b2  = (const float*)d_in[7];
    const float* g2  = (const float*)d_in[8];
    const float* be2 = (const float*)d_in[9];
    const float* W3  = (const float*)d_in[10];
    const float* b3  = (const float*)d_in[11];
    int E = in_sizes[1] / 2;
    const int* src = ei;
    const int* dst = ei + E;
    float* out = (float*)d_out;

    void *pA, *pB, *pH3, *pS, *pSc, *pSh;
    cudaGetSymbolAddress(&pA,  g_bufA);
    cudaGetSymbolAddress(&pB,  g_bufB);
    cudaGetSymbolAddress(&pH3, g_hw3);
    cudaGetSymbolAddress(&pS,  g_sums);
    cudaGetSymbolAddress(&pSc, g_scale);
    cudaGetSymbolAddress(&pSh, g_shift);
    float4* bufA = (float4*)pA;
    float4* bufB = (float4*)pB;
    float4* hw3  = (float4*)pH3;
    float* sums  = (float*)pS;
    float* scale = (float*)pSc;
    float* shift = (float*)pSh;

    const int n4_128 = NNODES * 32;
    const int GB128  = n4_128 / 256;
    const int GN     = (NNODES + 255) / 256;
    const int GE     = (E + 255) / 256;
    const int GROW   = NNODES / 8;               // 12500, exact
    const int GM2    = (NNODES + 255) / 256;     // 391

    const int SM128 = (16 * 4 * 130 + 2 * 2 * 4 * 258) * (int)sizeof(float4);  // 199168
    const int SM64  = (16 * 4 * 66  + 2 * 2 * 4 * 258) * (int)sizeof(float4);  // 133632
    cudaFuncSetAttribute(sgemm_tf32b<128>, cudaFuncAttributeMaxDynamicSharedMemorySize, SM128);
    cudaFuncSetAttribute(sgemm_tf32b<64>,  cudaFuncAttributeMaxDynamicSharedMemorySize, SM64);

    // preprocessing (layer-1 GEMM kept at launch #4 so ncu captures it)
    k_zero  <<<GN, 256>>>();
    k_degree<<<GE, 256>>>(dst, E);
    k_keys  <<<1, 32>>>();
    sgemm_tf32b<128><<<GM2, 512, SM128>>>(x, W1, (float*)bufA, NNODES, 128);
    k_dinv      <<<GN, 256>>>();
    k_scan_local<<<SCAN_BLOCKS, 256>>>();
    k_scan_block<<<1, 512>>>();
    k_scan_add  <<<SCAN_BLOCKS, 256>>>(E);
    k_fill      <<<GE, 256>>>(src, dst, E);

    // ---- layer 1 ----
    spmm128s<<<GROW, 256>>>(bufA, bufB, b1, sums);
    k_bnfinal<<<1, 128>>>(sums, g1, be1, scale, shift);
    k_bndrop<<<GB128, 256>>>(bufB, bufA, scale, shift, 0, n4_128);

    // ---- layer 2 ----
    sgemm_tf32b<128><<<GM2, 512, SM128>>>((const float*)bufA, W2, (float*)bufB, NNODES, 128);
    spmm128s<<<GROW, 256>>>(bufB, bufA, b2, sums + 256);
    k_bnfinal<<<1, 128>>>(sums + 256, g2, be2, scale + 128, shift + 128);
    k_bndrop<<<GB128, 256>>>(bufA, bufB, scale + 128, shift + 128, 1, n4_128);

    // ---- layer 3 + fused log_softmax ----
    sgemm_tf32b<64><<<GM2, 512, SM64>>>((const float*)bufB, W3, (float*)hw3, NNODES, 40);
    spmm40ls<<<GROW, 256>>>(hw3, out, b3);
}

// round 9
// speedup vs baseline: 1.2585x; 1.2585x over previous
#include <cuda_runtime.h>
#include <cstdint>

#define NNODES 100000
#define MAXE   1000000

// ---------------- scratch (static __device__ globals; no allocation) -------
__device__ __align__(16) float4 g_bufA[NNODES * 32];   // 100000 x 128 floats
__device__ __align__(16) float4 g_bufB[NNODES * 32];   // 100000 x 128 floats
__device__ __align__(16) float4 g_hw3 [NNODES * 10];   // 100000 x 40 floats
__device__ float g_dinv[NNODES];
__device__ int   g_icnt[NNODES];
__device__ int   g_fc  [NNODES];
__device__ int   g_rs  [NNODES + 1];
__device__ int   g_perm[MAXE];
__device__ int   g_bsum[512];
__device__ int   g_boff[512];
__device__ float g_sums[512];
__device__ __align__(16) float g_scale[256];
__device__ __align__(16) float g_shift[256];
__device__ unsigned g_keys[4];

#define SCAN_BLOCKS 391

// ---------------- threefry2x32 (JAX-exact, 20 rounds) ----------------------
__device__ __forceinline__ void tf_round(uint32_t &x0, uint32_t &x1, int r) {
    x0 += x1;
    x1 = __funnelshift_l(x1, x1, r);
    x1 ^= x0;
}

__device__ __forceinline__ uint2 tf_full(uint32_t k0, uint32_t k1, uint32_t x0, uint32_t x1) {
    uint32_t k2 = k0 ^ k1 ^ 0x1BD11BDAu;
    x0 += k0; x1 += k1;
    tf_round(x0,x1,13); tf_round(x0,x1,15); tf_round(x0,x1,26); tf_round(x0,x1,6);
    x0 += k1; x1 += k2 + 1u;
    tf_round(x0,x1,17); tf_round(x0,x1,29); tf_round(x0,x1,16); tf_round(x0,x1,24);
    x0 += k2; x1 += k0 + 2u;
    tf_round(x0,x1,13); tf_round(x0,x1,15); tf_round(x0,x1,26); tf_round(x0,x1,6);
    x0 += k0; x1 += k1 + 3u;
    tf_round(x0,x1,17); tf_round(x0,x1,29); tf_round(x0,x1,16); tf_round(x0,x1,24);
    x0 += k1; x1 += k2 + 4u;
    tf_round(x0,x1,13); tf_round(x0,x1,15); tf_round(x0,x1,26); tf_round(x0,x1,6);
    x0 += k2; x1 += k0 + 5u;
    return make_uint2(x0, x1);
}

__device__ __forceinline__ uint32_t tf_bits_xor(uint32_t k0, uint32_t k1, uint32_t k2, uint32_t ctr) {
    uint32_t x0 = k0;
    uint32_t x1 = ctr + k1;
    tf_round(x0,x1,13); tf_round(x0,x1,15); tf_round(x0,x1,26); tf_round(x0,x1,6);
    x0 += k1; x1 += k2 + 1u;
    tf_round(x0,x1,17); tf_round(x0,x1,29); tf_round(x0,x1,16); tf_round(x0,x1,24);
    x0 += k2; x1 += k0 + 2u;
    tf_round(x0,x1,13); tf_round(x0,x1,15); tf_round(x0,x1,26); tf_round(x0,x1,6);
    x0 += k0; x1 += k1 + 3u;
    tf_round(x0,x1,17); tf_round(x0,x1,29); tf_round(x0,x1,16); tf_round(x0,x1,24);
    x0 += k1; x1 += k2 + 4u;
    tf_round(x0,x1,13); tf_round(x0,x1,15); tf_round(x0,x1,26); tf_round(x0,x1,6);
    x0 += k2; x1 += k0 + 5u;
    return x0 ^ x1;
}

__global__ void k_keys() {
    if (threadIdx.x == 0) {
        uint2 a = tf_full(0u, 42u, 0u, 0u);
        uint2 b = tf_full(0u, 42u, 0u, 1u);
        g_keys[0] = a.x; g_keys[1] = a.y;
        g_keys[2] = b.x; g_keys[3] = b.y;
    }
}

// ---------------- graph preprocessing --------------------------------------
__global__ void k_zero() {
    int i = blockIdx.x * 256 + threadIdx.x;
    if (i < NNODES) { g_icnt[i] = 0; g_fc[i] = 0; }
    if (i < 512)    g_sums[i] = 0.f;
}

__global__ void k_degree(const int* __restrict__ dst, int E) {
    int e = blockIdx.x * 256 + threadIdx.x;
    if (e < E) atomicAdd(&g_icnt[dst[e]], 1);
}

__global__ void k_dinv() {
    int i = blockIdx.x * 256 + threadIdx.x;
    if (i < NNODES) g_dinv[i] = rsqrtf((float)g_icnt[i] + 1.0f);
}

__global__ __launch_bounds__(256) void k_scan_local() {
    __shared__ int s[256];
    int t = threadIdx.x;
    int i = blockIdx.x * 256 + t;
    int v = (i < NNODES) ? g_icnt[i] : 0;
    s[t] = v;
    __syncthreads();
#pragma unroll
    for (int off = 1; off < 256; off <<= 1) {
        int add = (t >= off) ? s[t - off] : 0;
        __syncthreads();
        s[t] += add;
        __syncthreads();
    }
    if (i < NNODES) g_rs[i] = s[t] - v;
    if (t == 255) g_bsum[blockIdx.x] = s[255];
}

__global__ __launch_bounds__(512) void k_scan_block() {
    __shared__ int s[512];
    int t = threadIdx.x;
    int v = (t < SCAN_BLOCKS) ? g_bsum[t] : 0;
    s[t] = v;
    __syncthreads();
#pragma unroll
    for (int off = 1; off < 512; off <<= 1) {
        int add = (t >= off) ? s[t - off] : 0;
        __syncthreads();
        s[t] += add;
        __syncthreads();
    }
    g_boff[t] = s[t] - v;
}

__global__ void k_scan_add(int E) {
    int i = blockIdx.x * 256 + threadIdx.x;
    if (i < NNODES) g_rs[i] += g_boff[blockIdx.x];
    if (i == NNODES) g_rs[NNODES] = E;
}

__global__ void k_fill(const int* __restrict__ src, const int* __restrict__ dst, int E) {
    int e = blockIdx.x * 256 + threadIdx.x;
    if (e >= E) return;
    int d = dst[e];
    int pos = g_rs[d] + atomicAdd(&g_fc[d], 1);
    g_perm[pos] = src[e];
}

// ---------------- TF32 split-MMA GEMM, B resident + A double-buffered ------
__device__ __forceinline__ uint32_t f2tf32(float x) {
    uint32_t r;
    asm("cvt.rna.tf32.f32 %0, %1;" : "=r"(r) : "f"(x));
    return r;
}
__device__ __forceinline__ float f2tf32f(float x) {
    return __uint_as_float(f2tf32(x));
}

#define MMA_TF32(cc, a0,a1,a2,a3, b0,b1)                                       \
    asm volatile("mma.sync.aligned.m16n8k8.row.col.f32.tf32.tf32.f32 "         \
                 "{%0,%1,%2,%3}, {%4,%5,%6,%7}, {%8,%9}, {%0,%1,%2,%3};"       \
                 : "+f"(cc[0]), "+f"(cc[1]), "+f"(cc[2]), "+f"(cc[3])          \
                 : "r"(a0), "r"(a1), "r"(a2), "r"(a3), "r"(b0), "r"(b1))

template<int NCPAD>
__global__ __launch_bounds__(512) void sgemm_tf32b(
    const float* __restrict__ A, const float* __restrict__ B,
    float* __restrict__ C, int M, int NC)
{
    constexpr int NT = NCPAD / 16;
    extern __shared__ float4 sm4[];
    float4* Bp = sm4;                          // [16][4][NCPAD+2]
    float4* Ap = sm4 + 16 * 4 * (NCPAD + 2);   // [2][2][4][258]

    int tid  = threadIdx.x;
    int warp = tid >> 5, lane = tid & 31;
    int wm = warp >> 1, wn = warp & 1;
    int gid = lane >> 2, ctid = lane & 3;
    int row0 = blockIdx.x * 256;
    int wr = wm * 32;
    int wc = wn * (NCPAD / 2);

    float c[2][NT][4];
#pragma unroll
    for (int mt = 0; mt < 2; mt++)
#pragma unroll
        for (int nt = 0; nt < NT; nt++)
#pragma unroll
            for (int j = 0; j < 4; j++) c[mt][nt][j] = 0.f;

    for (int idx = tid; idx < 64 * NCPAD; idx += 512) {
        int cc = idx & (NCPAD - 1);
        int s  = idx / NCPAD;
        int g = s >> 2, t = s & 3;
        int k = g * 8 + t;
        float a0 = (cc < NC) ? B[k * NC + cc] : 0.f;
        float a1 = (cc < NC) ? B[(k + 4) * NC + cc] : 0.f;
        float h0 = f2tf32f(a0), h1 = f2tf32f(a1);
        Bp[(g * 4 + t) * (NCPAD + 2) + cc] =
            make_float4(h0, h1, f2tf32f(a0 - h0), f2tf32f(a1 - h1));
    }

    int ar = tid >> 1, ag = tid & 1;
    int gr = row0 + ar;
    const float* Arow = A + gr * 128 + ag * 8;

    auto storeA = [&](int buf, float4 v0, float4 v1) {
        float vv[8] = {v0.x, v0.y, v0.z, v0.w, v1.x, v1.y, v1.z, v1.w};
        float h[8], l[8];
#pragma unroll
        for (int t = 0; t < 8; t++) {
            h[t] = f2tf32f(vv[t]);
            l[t] = f2tf32f(vv[t] - h[t]);
        }
#pragma unroll
        for (int t = 0; t < 4; t++)
            Ap[((buf * 2 + ag) * 4 + t) * 258 + ar] =
                make_float4(h[t], h[t + 4], l[t], l[t + 4]);
    };

    {
        float4 v0 = make_float4(0.f,0.f,0.f,0.f), v1 = v0;
        if (gr < M) { v0 = *(const float4*)(Arow); v1 = *(const float4*)(Arow + 4); }
        storeA(0, v0, v1);
    }
    __syncthreads();

    for (int it = 0; it < 8; it++) {
        int b = it & 1;
        float4 p0 = make_float4(0.f,0.f,0.f,0.f), p1 = p0;
        if (it < 7 && gr < M) {
            p0 = *(const float4*)(Arow + (it + 1) * 16);
            p1 = *(const float4*)(Arow + (it + 1) * 16 + 4);
        }
#pragma unroll
        for (int g = 0; g < 2; g++) {
            int G = it * 2 + g;
            const float4* Abase = Ap + ((b * 2 + g) * 4 + ctid) * 258;
            float4 alo0 = Abase[wr + gid];
            float4 ahi0 = Abase[wr + gid + 8];
            float4 alo1 = Abase[wr + 16 + gid];
            float4 ahi1 = Abase[wr + 16 + gid + 8];
            uint32_t ah0[4] = {__float_as_uint(alo0.x), __float_as_uint(ahi0.x),
                               __float_as_uint(alo0.y), __float_as_uint(ahi0.y)};
            uint32_t al0[4] = {__float_as_uint(alo0.z), __float_as_uint(ahi0.z),
                               __float_as_uint(alo0.w), __float_as_uint(ahi0.w)};
            uint32_t ah1[4] = {__float_as_uint(alo1.x), __float_as_uint(ahi1.x),
                               __float_as_uint(alo1.y), __float_as_uint(ahi1.y)};
            uint32_t al1[4] = {__float_as_uint(alo1.z), __float_as_uint(ahi1.z),
                               __float_as_uint(alo1.w), __float_as_uint(ahi1.w)};
            const float4* Bbase = Bp + (G * 4 + ctid) * (NCPAD + 2) + wc;
#pragma unroll
            for (int nt = 0; nt < NT; nt++) {
                float4 bb = Bbase[nt * 8 + gid];
                uint32_t bh0 = __float_as_uint(bb.x), bh1 = __float_as_uint(bb.y);
                uint32_t bl0 = __float_as_uint(bb.z), bl1 = __float_as_uint(bb.w);
                MMA_TF32(c[0][nt], ah0[0], ah0[1], ah0[2], ah0[3], bh0, bh1);
                MMA_TF32(c[0][nt], al0[0], al0[1], al0[2], al0[3], bh0, bh1);
                MMA_TF32(c[0][nt], ah0[0], ah0[1], ah0[2], ah0[3], bl0, bl1);
                MMA_TF32(c[1][nt], ah1[0], ah1[1], ah1[2], ah1[3], bh0, bh1);
                MMA_TF32(c[1][nt], al1[0], al1[1], al1[2], al1[3], bh0, bh1);
                MMA_TF32(c[1][nt], ah1[0], ah1[1], ah1[2], ah1[3], bl0, bl1);
            }
        }
        if (it < 7) {
            storeA(b ^ 1, p0, p1);
            __syncthreads();
        }
    }

#pragma unroll
    for (int mt = 0; mt < 2; mt++) {
        int r0 = row0 + wr + mt * 16 + gid;
        int r1 = r0 + 8;
#pragma unroll
        for (int nt = 0; nt < NT; nt++) {
            int ccol = wc + nt * 8 + ctid * 2;
            if (ccol < NC) {
                if (r0 < M) *(float2*)(C + r0 * NC + ccol) = make_float2(c[mt][nt][0], c[mt][nt][1]);
                if (r1 < M) *(float2*)(C + r1 * NC + ccol) = make_float2(c[mt][nt][2], c[mt][nt][3]);
            }
        }
    }
}

// ---------------- CSR SpMM (no atomics): agg = Anorm*hw + self + bias ------
__global__ __launch_bounds__(256) void spmm128(
    const float4* __restrict__ hw, float4* __restrict__ agg,
    const float* __restrict__ bias)
{
    int row = blockIdx.x * 8 + (threadIdx.x >> 5);
    if (row >= NNODES) return;
    int lane = threadIdx.x & 31;
    int beg = __ldg(&g_rs[row]);
    int end = __ldg(&g_rs[row + 1]);
    float di = g_dinv[row];
    float di2 = di * di;

    float4 self = __ldg(hw + row * 32 + lane);
    float4 b = ((const float4*)bias)[lane];
    float4 acc  = make_float4(fmaf(self.x, di2, b.x), fmaf(self.y, di2, b.y),
                              fmaf(self.z, di2, b.z), fmaf(self.w, di2, b.w));
    float4 acc2 = make_float4(0.f, 0.f, 0.f, 0.f);

    int j = beg;
    for (; j + 1 < end; j += 2) {
        int s0 = __ldg(&g_perm[j]);
        int s1 = __ldg(&g_perm[j + 1]);
        float n0 = __ldg(&g_dinv[s0]) * di;
        float n1 = __ldg(&g_dinv[s1]) * di;
        float4 v0 = __ldg(hw + s0 * 32 + lane);
        float4 v1 = __ldg(hw + s1 * 32 + lane);
        acc.x  = fmaf(v0.x, n0, acc.x);  acc.y  = fmaf(v0.y, n0, acc.y);
        acc.z  = fmaf(v0.z, n0, acc.z);  acc.w  = fmaf(v0.w, n0, acc.w);
        acc2.x = fmaf(v1.x, n1, acc2.x); acc2.y = fmaf(v1.y, n1, acc2.y);
        acc2.z = fmaf(v1.z, n1, acc2.z); acc2.w = fmaf(v1.w, n1, acc2.w);
    }
    if (j < end) {
        int s0 = __ldg(&g_perm[j]);
        float n0 = __ldg(&g_dinv[s0]) * di;
        float4 v0 = __ldg(hw + s0 * 32 + lane);
        acc.x = fmaf(v0.x, n0, acc.x); acc.y = fmaf(v0.y, n0, acc.y);
        acc.z = fmaf(v0.z, n0, acc.z); acc.w = fmaf(v0.w, n0, acc.w);
    }
    agg[row * 32 + lane] = make_float4(acc.x + acc2.x, acc.y + acc2.y,
                                       acc.z + acc2.z, acc.w + acc2.w);
}

// ---------------- fused SpMM(40) + log_softmax -----------------------------
__global__ __launch_bounds__(256) void spmm40ls(
    const float4* __restrict__ hw, float* __restrict__ out,
    const float* __restrict__ bias)
{
    int row = blockIdx.x * 8 + (threadIdx.x >> 5);
    int lane = threadIdx.x & 31;
    bool act = (lane < 10);
    int lc = act ? lane : 9;
    int beg = __ldg(&g_rs[row]);
    int end = __ldg(&g_rs[row + 1]);
    float di = g_dinv[row];
    float di2 = di * di;

    float4 self = __ldg(hw + row * 10 + lc);
    float4 b = ((const float4*)bias)[lc];
    float4 acc = make_float4(fmaf(self.x, di2, b.x), fmaf(self.y, di2, b.y),
                             fmaf(self.z, di2, b.z), fmaf(self.w, di2, b.w));
    for (int j = beg; j < end; j++) {
        int s = __ldg(&g_perm[j]);
        float n = __ldg(&g_dinv[s]) * di;
        float4 v = __ldg(hw + s * 10 + lc);
        acc.x = fmaf(v.x, n, acc.x); acc.y = fmaf(v.y, n, acc.y);
        acc.z = fmaf(v.z, n, acc.z); acc.w = fmaf(v.w, n, acc.w);
    }
    float mx = act ? fmaxf(fmaxf(acc.x, acc.y), fmaxf(acc.z, acc.w)) : -3.4e38f;
#pragma unroll
    for (int o = 16; o; o >>= 1) mx = fmaxf(mx, __shfl_xor_sync(0xffffffffu, mx, o));
    float s = act ? (expf(acc.x - mx) + expf(acc.y - mx) +
                     expf(acc.z - mx) + expf(acc.w - mx)) : 0.f;
#pragma unroll
    for (int o = 16; o; o >>= 1) s += __shfl_xor_sync(0xffffffffu, s, o);
    float l = mx + logf(s);
    if (act)
        ((float4*)out)[row * 10 + lane] =
            make_float4(acc.x - l, acc.y - l, acc.z - l, acc.w - l);
}

// ---------------- batchnorm stats + finalize -------------------------------
__global__ __launch_bounds__(256) void k_bnstats(const float* __restrict__ h,
                                                 float* __restrict__ sums) {
    __shared__ float ss[256], sq[256];
    int tid = threadIdx.x;
    int c = tid & 127;
    int half = tid >> 7;
    int rbeg = blockIdx.x * 125;        // grid = 800, covers exactly 100000
    float s = 0.f, q = 0.f;
    for (int r = rbeg + half; r < rbeg + 125; r += 2) {
        float v = h[r * 128 + c];
        s += v;
        q = fmaf(v, v, q);
    }
    ss[tid] = s; sq[tid] = q;
    __syncthreads();
    if (half == 0) {
        atomicAdd(&sums[c],       ss[tid] + ss[tid + 128]);
        atomicAdd(&sums[128 + c], sq[tid] + sq[tid + 128]);
    }
}

__global__ void k_bnfinal(const float* __restrict__ sums,
                          const float* __restrict__ gamma, const float* __restrict__ beta,
                          float* __restrict__ sc, float* __restrict__ sh) {
    int c = threadIdx.x;
    const float inv_n = 1.0f / (float)NNODES;
    float mean = sums[c] * inv_n;
    float var  = sums[128 + c] * inv_n - mean * mean;
    var = fmaxf(var, 0.f);
    float rstd = rsqrtf(var + 1e-5f);
    float a = gamma[c] * rstd;
    sc[c] = a;
    sh[c] = beta[c] - mean * a;
}

// ---------------- fused BN + ReLU + exact threefry dropout -----------------
__global__ __launch_bounds__(256) void k_bndrop(
    const float4* __restrict__ in, float4* __restrict__ out,
    const float* __restrict__ sc, const float* __restrict__ sh,
    int layer, int n4)
{
    int t = blockIdx.x * 256 + threadIdx.x;
    if (t >= n4) return;
    uint32_t k0 = g_keys[layer * 2 + 0];
    uint32_t k1 = g_keys[layer * 2 + 1];
    uint32_t k2 = k0 ^ k1 ^ 0x1BD11BDAu;

    int c = (t & 31) * 4;
    float4 v = in[t];
    float4 a = *(const float4*)(sc + c);
    float4 b = *(const float4*)(sh + c);

    float r0 = fmaxf(fmaf(v.x, a.x, b.x), 0.f);
    float r1 = fmaxf(fmaf(v.y, a.y, b.y), 0.f);
    float r2 = fmaxf(fmaf(v.z, a.z, b.z), 0.f);
    float r3 = fmaxf(fmaf(v.w, a.w, b.w), 0.f);

    uint32_t i0 = (uint32_t)t * 4u;
    uint32_t m0 = tf_bits_xor(k0, k1, k2, i0 + 0u);
    uint32_t m1 = tf_bits_xor(k0, k1, k2, i0 + 1u);
    uint32_t m2 = tf_bits_xor(k0, k1, k2, i0 + 2u);
    uint32_t m3 = tf_bits_xor(k0, k1, k2, i0 + 3u);

    v.x = (m0 & 0x80000000u) ? 0.f : r0 + r0;
    v.y = (m1 & 0x80000000u) ? 0.f : r1 + r1;
    v.z = (m2 & 0x80000000u) ? 0.f : r2 + r2;
    v.w = (m3 & 0x80000000u) ? 0.f : r3 + r3;
    out[t] = v;
}

// ---------------- launch ---------------------------------------------------
extern "C" void kernel_launch(void* const* d_in, const int* in_sizes, int n_in,
                              void* d_out, int out_size) {
    const float* x   = (const float*)d_in[0];
    const int*   ei  = (const int*)  d_in[1];
    const float* W1  = (const float*)d_in[2];
    const float* b1  = (const float*)d_in[3];
    const float* g1  = (const float*)d_in[4];
    const float* be1 = (const float*)d_in[5];
    const float* W2  = (const float*)d_in[6];
    const float* b2  = (const float*)d_in[7];
    const float* g2  = (const float*)d_in[8];
    const float* be2 = (const float*)d_in[9];
    const float* W3  = (const float*)d_in[10];
    const float* b3  = (const float*)d_in[11];
    int E = in_sizes[1] / 2;
    const int* src = ei;
    const int* dst = ei + E;
    float* out = (float*)d_out;

    void *pA, *pB, *pH3, *pS, *pSc, *pSh;
    cudaGetSymbolAddress(&pA,  g_bufA);
    cudaGetSymbolAddress(&pB,  g_bufB);
    cudaGetSymbolAddress(&pH3, g_hw3);
    cudaGetSymbolAddress(&pS,  g_sums);
    cudaGetSymbolAddress(&pSc, g_scale);
    cudaGetSymbolAddress(&pSh, g_shift);
    float4* bufA = (float4*)pA;
    float4* bufB = (float4*)pB;
    float4* hw3  = (float4*)pH3;
    float* sums  = (float*)pS;
    float* scale = (float*)pSc;
    float* shift = (float*)pSh;

    const int n4_128 = NNODES * 32;
    const int GB128  = n4_128 / 256;
    const int GN     = (NNODES + 255) / 256;
    const int GE     = (E + 255) / 256;
    const int GROW   = NNODES / 8;               // 12500
    const int GM2    = (NNODES + 255) / 256;     // 391

    const int SM128 = (16 * 4 * 130 + 2 * 2 * 4 * 258) * (int)sizeof(float4);  // 199168
    const int SM64  = (16 * 4 * 66  + 2 * 2 * 4 * 258) * (int)sizeof(float4);  // 133632
    cudaFuncSetAttribute(sgemm_tf32b<128>, cudaFuncAttributeMaxDynamicSharedMemorySize, SM128);
    cudaFuncSetAttribute(sgemm_tf32b<64>,  cudaFuncAttributeMaxDynamicSharedMemorySize, SM64);

    // preprocessing (layer-1 GEMM kept at launch #4 so ncu captures it)
    k_zero  <<<GN, 256>>>();
    k_degree<<<GE, 256>>>(dst, E);
    k_keys  <<<1, 32>>>();
    sgemm_tf32b<128><<<GM2, 512, SM128>>>(x, W1, (float*)bufA, NNODES, 128);
    k_dinv      <<<GN, 256>>>();
    k_scan_local<<<SCAN_BLOCKS, 256>>>();
    k_scan_block<<<1, 512>>>();
    k_scan_add  <<<SCAN_BLOCKS, 256>>>(E);
    k_fill      <<<GE, 256>>>(src, dst, E);

    // ---- layer 1 ----
    spmm128 <<<GROW, 256>>>(bufA, bufB, b1);
    k_bnstats<<<800, 256>>>((const float*)bufB, sums);
    k_bnfinal<<<1, 128>>>(sums, g1, be1, scale, shift);
    k_bndrop<<<GB128, 256>>>(bufB, bufA, scale, shift, 0, n4_128);

    // ---- layer 2 ----
    sgemm_tf32b<128><<<GM2, 512, SM128>>>((const float*)bufA, W2, (float*)bufB, NNODES, 128);
    spmm128 <<<GROW, 256>>>(bufB, bufA, b2);
    k_bnstats<<<800, 256>>>((const float*)bufA, sums + 256);
    k_bnfinal<<<1, 128>>>(sums + 256, g2, be2, scale + 128, shift + 128);
    k_bndrop<<<GB128, 256>>>(bufA, bufB, scale + 128, shift + 128, 1, n4_128);

    // ---- layer 3 + fused log_softmax ----
    sgemm_tf32b<64><<<GM2, 512, SM64>>>((const float*)bufB, W3, (float*)hw3, NNODES, 40);
    spmm40ls<<<GROW, 256>>>(hw3, out, b3);
}

// round 10
// speedup vs baseline: 1.2715x; 1.0104x over previous
#include <cuda_runtime.h>
#include <cstdint>

#define NNODES 100000
#define MAXE   1000000

// ---------------- scratch (static __device__ globals; no allocation) -------
__device__ __align__(16) float4 g_bufA[NNODES * 32];   // 100000 x 128 floats
__device__ __align__(16) float4 g_bufB[NNODES * 32];   // 100000 x 128 floats
__device__ __align__(16) float4 g_hw3 [NNODES * 10];   // 100000 x 40 floats
__device__ float g_dinv[NNODES];
__device__ int   g_icnt[NNODES];
__device__ int   g_fc  [NNODES];
__device__ int   g_rs  [NNODES + 1];
__device__ int   g_perm[MAXE];
__device__ int   g_bsum[512];
__device__ int   g_boff[512];
__device__ float g_sums[512];
__device__ __align__(16) float g_scale[256];
__device__ __align__(16) float g_shift[256];
__device__ unsigned g_keys[4];

#define SCAN_BLOCKS 391

// ---------------- threefry2x32 (JAX-exact, 20 rounds) ----------------------
__device__ __forceinline__ void tf_round(uint32_t &x0, uint32_t &x1, int r) {
    x0 += x1;
    x1 = __funnelshift_l(x1, x1, r);
    x1 ^= x0;
}

__device__ __forceinline__ uint2 tf_full(uint32_t k0, uint32_t k1, uint32_t x0, uint32_t x1) {
    uint32_t k2 = k0 ^ k1 ^ 0x1BD11BDAu;
    x0 += k0; x1 += k1;
    tf_round(x0,x1,13); tf_round(x0,x1,15); tf_round(x0,x1,26); tf_round(x0,x1,6);
    x0 += k1; x1 += k2 + 1u;
    tf_round(x0,x1,17); tf_round(x0,x1,29); tf_round(x0,x1,16); tf_round(x0,x1,24);
    x0 += k2; x1 += k0 + 2u;
    tf_round(x0,x1,13); tf_round(x0,x1,15); tf_round(x0,x1,26); tf_round(x0,x1,6);
    x0 += k0; x1 += k1 + 3u;
    tf_round(x0,x1,17); tf_round(x0,x1,29); tf_round(x0,x1,16); tf_round(x0,x1,24);
    x0 += k1; x1 += k2 + 4u;
    tf_round(x0,x1,13); tf_round(x0,x1,15); tf_round(x0,x1,26); tf_round(x0,x1,6);
    x0 += k2; x1 += k0 + 5u;
    return make_uint2(x0, x1);
}

__device__ __forceinline__ uint32_t tf_bits_xor(uint32_t k0, uint32_t k1, uint32_t k2, uint32_t ctr) {
    uint32_t x0 = k0;
    uint32_t x1 = ctr + k1;
    tf_round(x0,x1,13); tf_round(x0,x1,15); tf_round(x0,x1,26); tf_round(x0,x1,6);
    x0 += k1; x1 += k2 + 1u;
    tf_round(x0,x1,17); tf_round(x0,x1,29); tf_round(x0,x1,16); tf_round(x0,x1,24);
    x0 += k2; x1 += k0 + 2u;
    tf_round(x0,x1,13); tf_round(x0,x1,15); tf_round(x0,x1,26); tf_round(x0,x1,6);
    x0 += k0; x1 += k1 + 3u;
    tf_round(x0,x1,17); tf_round(x0,x1,29); tf_round(x0,x1,16); tf_round(x0,x1,24);
    x0 += k1; x1 += k2 + 4u;
    tf_round(x0,x1,13); tf_round(x0,x1,15); tf_round(x0,x1,26); tf_round(x0,x1,6);
    x0 += k2; x1 += k0 + 5u;
    return x0 ^ x1;
}

__global__ void k_keys() {
    if (threadIdx.x == 0) {
        uint2 a = tf_full(0u, 42u, 0u, 0u);
        uint2 b = tf_full(0u, 42u, 0u, 1u);
        g_keys[0] = a.x; g_keys[1] = a.y;
        g_keys[2] = b.x; g_keys[3] = b.y;
    }
}

// ---------------- graph preprocessing --------------------------------------
__global__ void k_zero() {
    int i = blockIdx.x * 256 + threadIdx.x;
    if (i < NNODES) { g_icnt[i] = 0; g_fc[i] = 0; }
    if (i < 512)    g_sums[i] = 0.f;
}

__global__ void k_degree(const int* __restrict__ dst, int E) {
    int e = blockIdx.x * 256 + threadIdx.x;
    if (e < E) atomicAdd(&g_icnt[dst[e]], 1);
}

__global__ void k_dinv() {
    int i = blockIdx.x * 256 + threadIdx.x;
    if (i < NNODES) g_dinv[i] = rsqrtf((float)g_icnt[i] + 1.0f);
}

__global__ __launch_bounds__(256) void k_scan_local() {
    __shared__ int s[256];
    int t = threadIdx.x;
    int i = blockIdx.x * 256 + t;
    int v = (i < NNODES) ? g_icnt[i] : 0;
    s[t] = v;
    __syncthreads();
#pragma unroll
    for (int off = 1; off < 256; off <<= 1) {
        int add = (t >= off) ? s[t - off] : 0;
        __syncthreads();
        s[t] += add;
        __syncthreads();
    }
    if (i < NNODES) g_rs[i] = s[t] - v;
    if (t == 255) g_bsum[blockIdx.x] = s[255];
}

__global__ __launch_bounds__(512) void k_scan_block() {
    __shared__ int s[512];
    int t = threadIdx.x;
    int v = (t < SCAN_BLOCKS) ? g_bsum[t] : 0;
    s[t] = v;
    __syncthreads();
#pragma unroll
    for (int off = 1; off < 512; off <<= 1) {
        int add = (t >= off) ? s[t - off] : 0;
        __syncthreads();
        s[t] += add;
        __syncthreads();
    }
    g_boff[t] = s[t] - v;
}

__global__ void k_scan_add(int E) {
    int i = blockIdx.x * 256 + threadIdx.x;
    if (i < NNODES) g_rs[i] += g_boff[blockIdx.x];
    if (i == NNODES) g_rs[NNODES] = E;
}

__global__ void k_fill(const int* __restrict__ src, const int* __restrict__ dst, int E) {
    int e = blockIdx.x * 256 + threadIdx.x;
    if (e >= E) return;
    int d = dst[e];
    int pos = g_rs[d] + atomicAdd(&g_fc[d], 1);
    g_perm[pos] = src[e];
}

// ---------------- TF32 split-MMA GEMM, B resident + A double-buffered ------
// DROP < 0: plain GEMM.  DROP = layer (0/1): A-staging applies fused
// BN(scale/shift) + ReLU + exact threefry dropout before the hi/lo split.
// Masks depend only on indices -> computed right after the prefetch LDGs so
// the threefry ALU work overlaps LDG latency + the MMA stream.
__device__ __forceinline__ uint32_t f2tf32(float x) {
    uint32_t r;
    asm("cvt.rna.tf32.f32 %0, %1;" : "=r"(r) : "f"(x));
    return r;
}
__device__ __forceinline__ float f2tf32f(float x) {
    return __uint_as_float(f2tf32(x));
}

#define MMA_TF32(cc, a0,a1,a2,a3, b0,b1)                                       \
    asm volatile("mma.sync.aligned.m16n8k8.row.col.f32.tf32.tf32.f32 "         \
                 "{%0,%1,%2,%3}, {%4,%5,%6,%7}, {%8,%9}, {%0,%1,%2,%3};"       \
                 : "+f"(cc[0]), "+f"(cc[1]), "+f"(cc[2]), "+f"(cc[3])          \
                 : "r"(a0), "r"(a1), "r"(a2), "r"(a3), "r"(b0), "r"(b1))

template<int NCPAD, int DROP>
__global__ __launch_bounds__(512) void sgemm_tf32b(
    const float* __restrict__ A, const float* __restrict__ B,
    float* __restrict__ C, int M, int NC)
{
    constexpr int NT = NCPAD / 16;
    extern __shared__ float4 sm4[];
    float4* Bp = sm4;                          // [16][4][NCPAD+2]
    float4* Ap = sm4 + 16 * 4 * (NCPAD + 2);   // [2][2][4][258]

    int tid  = threadIdx.x;
    int warp = tid >> 5, lane = tid & 31;
    int wm = warp >> 1, wn = warp & 1;
    int gid = lane >> 2, ctid = lane & 3;
    int row0 = blockIdx.x * 256;
    int wr = wm * 32;
    int wc = wn * (NCPAD / 2);

    uint32_t kk0 = 0, kk1 = 0, kk2 = 0;
    if (DROP >= 0) {
        kk0 = g_keys[DROP * 2 + 0];
        kk1 = g_keys[DROP * 2 + 1];
        kk2 = kk0 ^ kk1 ^ 0x1BD11BDAu;
    }

    float c[2][NT][4];
#pragma unroll
    for (int mt = 0; mt < 2; mt++)
#pragma unroll
        for (int nt = 0; nt < NT; nt++)
#pragma unroll
            for (int j = 0; j < 4; j++) c[mt][nt][j] = 0.f;

    for (int idx = tid; idx < 64 * NCPAD; idx += 512) {
        int cc = idx & (NCPAD - 1);
        int s  = idx / NCPAD;
        int g = s >> 2, t = s & 3;
        int k = g * 8 + t;
        float a0 = (cc < NC) ? B[k * NC + cc] : 0.f;
        float a1 = (cc < NC) ? B[(k + 4) * NC + cc] : 0.f;
        float h0 = f2tf32f(a0), h1 = f2tf32f(a1);
        Bp[(g * 4 + t) * (NCPAD + 2) + cc] =
            make_float4(h0, h1, f2tf32f(a0 - h0), f2tf32f(a1 - h1));
    }

    int ar = tid >> 1, ag = tid & 1;
    int gr = row0 + ar;
    const float* Arow = A + gr * 128 + ag * 8;

    // masks for the 8 staged channels of chunk with k-base k0c
    auto calcMasks = [&](int k0c, uint32_t* msk) {
        uint32_t ibase = (uint32_t)gr * 128u + (uint32_t)(k0c + ag * 8);
#pragma unroll
        for (int t = 0; t < 8; t++)
            msk[t] = tf_bits_xor(kk0, kk1, kk2, ibase + t);
    };

    // transform (BN+ReLU+drop) + hi/lo split + smem store
    auto storeA = [&](int buf, int k0c, float4 v0, float4 v1, const uint32_t* msk) {
        float vv[8] = {v0.x, v0.y, v0.z, v0.w, v1.x, v1.y, v1.z, v1.w};
        if (DROP >= 0) {
            int cb = k0c + ag * 8;
            float4 s0 = *(const float4*)(g_scale + DROP * 128 + cb);
            float4 s1 = *(const float4*)(g_scale + DROP * 128 + cb + 4);
            float4 t0 = *(const float4*)(g_shift + DROP * 128 + cb);
            float4 t1 = *(const float4*)(g_shift + DROP * 128 + cb + 4);
            float sc[8] = {s0.x, s0.y, s0.z, s0.w, s1.x, s1.y, s1.z, s1.w};
            float sh[8] = {t0.x, t0.y, t0.z, t0.w, t1.x, t1.y, t1.z, t1.w};
#pragma unroll
            for (int t = 0; t < 8; t++) {
                float r = fmaxf(fmaf(vv[t], sc[t], sh[t]), 0.f);
                vv[t] = (msk[t] & 0x80000000u) ? 0.f : r + r;
            }
        }
        float h[8], l[8];
#pragma unroll
        for (int t = 0; t < 8; t++) {
            h[t] = f2tf32f(vv[t]);
            l[t] = f2tf32f(vv[t] - h[t]);
        }
#pragma unroll
        for (int t = 0; t < 4; t++)
            Ap[((buf * 2 + ag) * 4 + t) * 258 + ar] =
                make_float4(h[t], h[t + 4], l[t], l[t + 4]);
    };

    {
        float4 v0 = make_float4(0.f,0.f,0.f,0.f), v1 = v0;
        if (gr < M) { v0 = *(const float4*)(Arow); v1 = *(const float4*)(Arow + 4); }
        uint32_t msk[8];
        if (DROP >= 0) calcMasks(0, msk);
        storeA(0, 0, v0, v1, msk);
    }
    __syncthreads();

    for (int it = 0; it < 8; it++) {
        int b = it & 1;
        float4 p0 = make_float4(0.f,0.f,0.f,0.f), p1 = p0;
        uint32_t msk[8];
        if (it < 7 && gr < M) {
            p0 = *(const float4*)(Arow + (it + 1) * 16);
            p1 = *(const float4*)(Arow + (it + 1) * 16 + 4);
        }
        if (DROP >= 0 && it < 7) calcMasks((it + 1) * 16, msk);
#pragma unroll
        for (int g = 0; g < 2; g++) {
            int G = it * 2 + g;
            const float4* Abase = Ap + ((b * 2 + g) * 4 + ctid) * 258;
            float4 alo0 = Abase[wr + gid];
            float4 ahi0 = Abase[wr + gid + 8];
            float4 alo1 = Abase[wr + 16 + gid];
            float4 ahi1 = Abase[wr + 16 + gid + 8];
            uint32_t ah0[4] = {__float_as_uint(alo0.x), __float_as_uint(ahi0.x),
                               __float_as_uint(alo0.y), __float_as_uint(ahi0.y)};
            uint32_t al0[4] = {__float_as_uint(alo0.z), __float_as_uint(ahi0.z),
                               __float_as_uint(alo0.w), __float_as_uint(ahi0.w)};
            uint32_t ah1[4] = {__float_as_uint(alo1.x), __float_as_uint(ahi1.x),
                               __float_as_uint(alo1.y), __float_as_uint(ahi1.y)};
            uint32_t al1[4] = {__float_as_uint(alo1.z), __float_as_uint(ahi1.z),
                               __float_as_uint(alo1.w), __float_as_uint(ahi1.w)};
            const float4* Bbase = Bp + (G * 4 + ctid) * (NCPAD + 2) + wc;
#pragma unroll
            for (int nt = 0; nt < NT; nt++) {
                float4 bb = Bbase[nt * 8 + gid];
                uint32_t bh0 = __float_as_uint(bb.x), bh1 = __float_as_uint(bb.y);
                uint32_t bl0 = __float_as_uint(bb.z), bl1 = __float_as_uint(bb.w);
                MMA_TF32(c[0][nt], ah0[0], ah0[1], ah0[2], ah0[3], bh0, bh1);
                MMA_TF32(c[0][nt], al0[0], al0[1], al0[2], al0[3], bh0, bh1);
                MMA_TF32(c[0][nt], ah0[0], ah0[1], ah0[2], ah0[3], bl0, bl1);
                MMA_TF32(c[1][nt], ah1[0], ah1[1], ah1[2], ah1[3], bh0, bh1);
                MMA_TF32(c[1][nt], al1[0], al1[1], al1[2], al1[3], bh0, bh1);
                MMA_TF32(c[1][nt], ah1[0], ah1[1], ah1[2], ah1[3], bl0, bl1);
            }
        }
        if (it < 7) {
            storeA(b ^ 1, (it + 1) * 16, p0, p1, msk);
            __syncthreads();
        }
    }

#pragma unroll
    for (int mt = 0; mt < 2; mt++) {
        int r0 = row0 + wr + mt * 16 + gid;
        int r1 = r0 + 8;
#pragma unroll
        for (int nt = 0; nt < NT; nt++) {
            int ccol = wc + nt * 8 + ctid * 2;
            if (ccol < NC) {
                if (r0 < M) *(float2*)(C + r0 * NC + ccol) = make_float2(c[mt][nt][0], c[mt][nt][1]);
                if (r1 < M) *(float2*)(C + r1 * NC + ccol) = make_float2(c[mt][nt][2], c[mt][nt][3]);
            }
        }
    }
}

// ---------------- CSR SpMM (no atomics): agg = Anorm*hw + self + bias ------
__global__ __launch_bounds__(256) void spmm128(
    const float4* __restrict__ hw, float4* __restrict__ agg,
    const float* __restrict__ bias)
{
    int row = blockIdx.x * 8 + (threadIdx.x >> 5);
    if (row >= NNODES) return;
    int lane = threadIdx.x & 31;
    int beg = __ldg(&g_rs[row]);
    int end = __ldg(&g_rs[row + 1]);
    float di = g_dinv[row];
    float di2 = di * di;

    float4 self = __ldg(hw + row * 32 + lane);
    float4 b = ((const float4*)bias)[lane];
    float4 acc  = make_float4(fmaf(self.x, di2, b.x), fmaf(self.y, di2, b.y),
                              fmaf(self.z, di2, b.z), fmaf(self.w, di2, b.w));
    float4 acc2 = make_float4(0.f, 0.f, 0.f, 0.f);

    int j = beg;
    for (; j + 1 < end; j += 2) {
        int s0 = __ldg(&g_perm[j]);
        int s1 = __ldg(&g_perm[j + 1]);
        float n0 = __ldg(&g_dinv[s0]) * di;
        float n1 = __ldg(&g_dinv[s1]) * di;
        float4 v0 = __ldg(hw + s0 * 32 + lane);
        float4 v1 = __ldg(hw + s1 * 32 + lane);
        acc.x  = fmaf(v0.x, n0, acc.x);  acc.y  = fmaf(v0.y, n0, acc.y);
        acc.z  = fmaf(v0.z, n0, acc.z);  acc.w  = fmaf(v0.w, n0, acc.w);
        acc2.x = fmaf(v1.x, n1, acc2.x); acc2.y = fmaf(v1.y, n1, acc2.y);
        acc2.z = fmaf(v1.z, n1, acc2.z); acc2.w = fmaf(v1.w, n1, acc2.w);
    }
    if (j < end) {
        int s0 = __ldg(&g_perm[j]);
        float n0 = __ldg(&g_dinv[s0]) * di;
        float4 v0 = __ldg(hw + s0 * 32 + lane);
        acc.x = fmaf(v0.x, n0, acc.x); acc.y = fmaf(v0.y, n0, acc.y);
        acc.z = fmaf(v0.z, n0, acc.z); acc.w = fmaf(v0.w, n0, acc.w);
    }
    agg[row * 32 + lane] = make_float4(acc.x + acc2.x, acc.y + acc2.y,
                                       acc.z + acc2.z, acc.w + acc2.w);
}

// ---------------- fused SpMM(40) + log_softmax -----------------------------
__global__ __launch_bounds__(256) void spmm40ls(
    const float4* __restrict__ hw, float* __restrict__ out,
    const float* __restrict__ bias)
{
    int row = blockIdx.x * 8 + (threadIdx.x >> 5);
    int lane = threadIdx.x & 31;
    bool act = (lane < 10);
    int lc = act ? lane : 9;
    int beg = __ldg(&g_rs[row]);
    int end = __ldg(&g_rs[row + 1]);
    float di = g_dinv[row];
    float di2 = di * di;

    float4 self = __ldg(hw + row * 10 + lc);
    float4 b = ((const float4*)bias)[lc];
    float4 acc = make_float4(fmaf(self.x, di2, b.x), fmaf(self.y, di2, b.y),
                             fmaf(self.z, di2, b.z), fmaf(self.w, di2, b.w));
    for (int j = beg; j < end; j++) {
        int s = __ldg(&g_perm[j]);
        float n = __ldg(&g_dinv[s]) * di;
        float4 v = __ldg(hw + s * 10 + lc);
        acc.x = fmaf(v.x, n, acc.x); acc.y = fmaf(v.y, n, acc.y);
        acc.z = fmaf(v.z, n, acc.z); acc.w = fmaf(v.w, n, acc.w);
    }
    float mx = act ? fmaxf(fmaxf(acc.x, acc.y), fmaxf(acc.z, acc.w)) : -3.4e38f;
#pragma unroll
    for (int o = 16; o; o >>= 1) mx = fmaxf(mx, __shfl_xor_sync(0xffffffffu, mx, o));
    float s = act ? (expf(acc.x - mx) + expf(acc.y - mx) +
                     expf(acc.z - mx) + expf(acc.w - mx)) : 0.f;
#pragma unroll
    for (int o = 16; o; o >>= 1) s += __shfl_xor_sync(0xffffffffu, s, o);
    float l = mx + logf(s);
    if (act)
        ((float4*)out)[row * 10 + lane] =
            make_float4(acc.x - l, acc.y - l, acc.z - l, acc.w - l);
}

// ---------------- batchnorm stats + finalize -------------------------------
__global__ __launch_bounds__(256) void k_bnstats(const float* __restrict__ h,
                                                 float* __restrict__ sums) {
    __shared__ float ss[256], sq[256];
    int tid = threadIdx.x;
    int c = tid & 127;
    int half = tid >> 7;
    int rbeg = blockIdx.x * 125;        // grid = 800, covers exactly 100000
    float s = 0.f, q = 0.f;
    for (int r = rbeg + half; r < rbeg + 125; r += 2) {
        float v = h[r * 128 + c];
        s += v;
        q = fmaf(v, v, q);
    }
    ss[tid] = s; sq[tid] = q;
    __syncthreads();
    if (half == 0) {
        atomicAdd(&sums[c],       ss[tid] + ss[tid + 128]);
        atomicAdd(&sums[128 + c], sq[tid] + sq[tid + 128]);
    }
}

__global__ void k_bnfinal(const float* __restrict__ sums,
                          const float* __restrict__ gamma, const float* __restrict__ beta,
                          float* __restrict__ sc, float* __restrict__ sh) {
    int c = threadIdx.x;
    const float inv_n = 1.0f / (float)NNODES;
    float mean = sums[c] * inv_n;
    float var  = sums[128 + c] * inv_n - mean * mean;
    var = fmaxf(var, 0.f);
    float rstd = rsqrtf(var + 1e-5f);
    float a = gamma[c] * rstd;
    sc[c] = a;
    sh[c] = beta[c] - mean * a;
}

// ---------------- launch ---------------------------------------------------
extern "C" void kernel_launch(void* const* d_in, const int* in_sizes, int n_in,
                              void* d_out, int out_size) {
    const float* x   = (const float*)d_in[0];
    const int*   ei  = (const int*)  d_in[1];
    const float* W1  = (const float*)d_in[2];
    const float* b1  = (const float*)d_in[3];
    const float* g1  = (const float*)d_in[4];
    const float* be1 = (const float*)d_in[5];
    const float* W2  = (const float*)d_in[6];
    const float* b2  = (const float*)d_in[7];
    const float* g2  = (const float*)d_in[8];
    const float* be2 = (const float*)d_in[9];
    const float* W3  = (const float*)d_in[10];
    const float* b3  = (const float*)d_in[11];
    int E = in_sizes[1] / 2;
    const int* src = ei;
    const int* dst = ei + E;
    float* out = (float*)d_out;

    void *pA, *pB, *pH3, *pS, *pSc, *pSh;
    cudaGetSymbolAddress(&pA,  g_bufA);
    cudaGetSymbolAddress(&pB,  g_bufB);
    cudaGetSymbolAddress(&pH3, g_hw3);
    cudaGetSymbolAddress(&pS,  g_sums);
    cudaGetSymbolAddress(&pSc, g_scale);
    cudaGetSymbolAddress(&pSh, g_shift);
    float4* bufA = (float4*)pA;
    float4* bufB = (float4*)pB;
    float4* hw3  = (float4*)pH3;
    float* sums  = (float*)pS;
    float* scale = (float*)pSc;
    float* shift = (float*)pSh;

    const int GN     = (NNODES + 255) / 256;
    const int GE     = (E + 255) / 256;
    const int GROW   = NNODES / 8;               // 12500
    const int GM2    = (NNODES + 255) / 256;     // 391

    const int SM128 = (16 * 4 * 130 + 2 * 2 * 4 * 258) * (int)sizeof(float4);  // 199168
    const int SM64  = (16 * 4 * 66  + 2 * 2 * 4 * 258) * (int)sizeof(float4);  // 133632
    cudaFuncSetAttribute(sgemm_tf32b<128,-1>, cudaFuncAttributeMaxDynamicSharedMemorySize, SM128);
    cudaFuncSetAttribute(sgemm_tf32b<128, 0>, cudaFuncAttributeMaxDynamicSharedMemorySize, SM128);
    cudaFuncSetAttribute(sgemm_tf32b<64,  1>, cudaFuncAttributeMaxDynamicSharedMemorySize, SM64);

    // preprocessing (layer-1 GEMM kept at launch #4 so ncu captures it)
    k_zero  <<<GN, 256>>>();
    k_degree<<<GE, 256>>>(dst, E);
    k_keys  <<<1, 32>>>();
    sgemm_tf32b<128,-1><<<GM2, 512, SM128>>>(x, W1, (float*)bufA, NNODES, 128);
    k_dinv      <<<GN, 256>>>();
    k_scan_local<<<SCAN_BLOCKS, 256>>>();
    k_scan_block<<<1, 512>>>();
    k_scan_add  <<<SCAN_BLOCKS, 256>>>(E);
    k_fill      <<<GE, 256>>>(src, dst, E);

    // ---- layer 1: spmm -> stats -> (BN+ReLU+drop fused into GEMM2) ----
    spmm128 <<<GROW, 256>>>(bufA, bufB, b1);
    k_bnstats<<<800, 256>>>((const float*)bufB, sums);
    k_bnfinal<<<1, 128>>>(sums, g1, be1, scale, shift);

    // ---- layer 2 ----
    sgemm_tf32b<128, 0><<<GM2, 512, SM128>>>((const float*)bufB, W2, (float*)bufA, NNODES, 128);
    spmm128 <<<GROW, 256>>>(bufA, bufB, b2);
    k_bnstats<<<800, 256>>>((const float*)bufB, sums + 256);
    k_bnfinal<<<1, 128>>>(sums + 256, g2, be2, scale + 128, shift + 128);

    // ---- layer 3 (drop fused) + fused log_softmax ----
    sgemm_tf32b<64, 1><<<GM2, 512, SM64>>>((const float*)bufB, W3, (float*)hw3, NNODES, 40);
    spmm40ls<<<GROW, 256>>>(hw3, out, b3);
}

// round 12
// speedup vs baseline: 1.3152x; 1.0343x over previous
#include <cuda_runtime.h>
#include <cstdint>

#define NNODES 100000
#define MAXE   1000000

// ---------------- scratch (static __device__ globals; no allocation) -------
__device__ __align__(16) float4 g_bufA[NNODES * 32];   // 100000 x 128 floats
__device__ __align__(16) float4 g_bufB[NNODES * 32];   // 100000 x 128 floats
__device__ __align__(16) float4 g_hw3 [NNODES * 10];   // 100000 x 40 floats
__device__ float g_dinv[NNODES];
__device__ int   g_icnt[NNODES];
__device__ int   g_fc  [NNODES];
__device__ int   g_rs  [NNODES + 1];
__device__ int   g_perm[MAXE];
__device__ int   g_bsum[512];
__device__ int   g_boff[512];
__device__ float g_sums[512];
__device__ __align__(16) float g_scale[256];
__device__ __align__(16) float g_shift[256];
__device__ unsigned g_keys[4];

#define SCAN_BLOCKS 391

// ---------------- threefry2x32 (JAX-exact, 20 rounds) ----------------------
__device__ __forceinline__ void tf_round(uint32_t &x0, uint32_t &x1, int r) {
    x0 += x1;
    x1 = __funnelshift_l(x1, x1, r);
    x1 ^= x0;
}

__device__ __forceinline__ uint2 tf_full(uint32_t k0, uint32_t k1, uint32_t x0, uint32_t x1) {
    uint32_t k2 = k0 ^ k1 ^ 0x1BD11BDAu;
    x0 += k0; x1 += k1;
    tf_round(x0,x1,13); tf_round(x0,x1,15); tf_round(x0,x1,26); tf_round(x0,x1,6);
    x0 += k1; x1 += k2 + 1u;
    tf_round(x0,x1,17); tf_round(x0,x1,29); tf_round(x0,x1,16); tf_round(x0,x1,24);
    x0 += k2; x1 += k0 + 2u;
    tf_round(x0,x1,13); tf_round(x0,x1,15); tf_round(x0,x1,26); tf_round(x0,x1,6);
    x0 += k0; x1 += k1 + 3u;
    tf_round(x0,x1,17); tf_round(x0,x1,29); tf_round(x0,x1,16); tf_round(x0,x1,24);
    x0 += k1; x1 += k2 + 4u;
    tf_round(x0,x1,13); tf_round(x0,x1,15); tf_round(x0,x1,26); tf_round(x0,x1,6);
    x0 += k2; x1 += k0 + 5u;
    return make_uint2(x0, x1);
}

__device__ __forceinline__ uint32_t tf_bits_xor(uint32_t k0, uint32_t k1, uint32_t k2, uint32_t ctr) {
    uint32_t x0 = k0;
    uint32_t x1 = ctr + k1;
    tf_round(x0,x1,13); tf_round(x0,x1,15); tf_round(x0,x1,26); tf_round(x0,x1,6);
    x0 += k1; x1 += k2 + 1u;
    tf_round(x0,x1,17); tf_round(x0,x1,29); tf_round(x0,x1,16); tf_round(x0,x1,24);
    x0 += k2; x1 += k0 + 2u;
    tf_round(x0,x1,13); tf_round(x0,x1,15); tf_round(x0,x1,26); tf_round(x0,x1,6);
    x0 += k0; x1 += k1 + 3u;
    tf_round(x0,x1,17); tf_round(x0,x1,29); tf_round(x0,x1,16); tf_round(x0,x1,24);
    x0 += k1; x1 += k2 + 4u;
    tf_round(x0,x1,13); tf_round(x0,x1,15); tf_round(x0,x1,26); tf_round(x0,x1,6);
    x0 += k2; x1 += k0 + 5u;
    return x0 ^ x1;
}

__global__ void k_keys() {
    if (threadIdx.x == 0) {
        uint2 a = tf_full(0u, 42u, 0u, 0u);
        uint2 b = tf_full(0u, 42u, 0u, 1u);
        g_keys[0] = a.x; g_keys[1] = a.y;
        g_keys[2] = b.x; g_keys[3] = b.y;
    }
}

// ---------------- graph preprocessing --------------------------------------
__global__ void k_zero() {
    int i = blockIdx.x * 256 + threadIdx.x;
    if (i < NNODES) { g_icnt[i] = 0; g_fc[i] = 0; }
    if (i < 512)    g_sums[i] = 0.f;
}

__global__ void k_degree(const int* __restrict__ dst, int E) {
    int e = blockIdx.x * 256 + threadIdx.x;
    if (e < E) atomicAdd(&g_icnt[dst[e]], 1);
}

__global__ void k_dinv() {
    int i = blockIdx.x * 256 + threadIdx.x;
    if (i < NNODES) g_dinv[i] = rsqrtf((float)g_icnt[i] + 1.0f);
}

__global__ __launch_bounds__(256) void k_scan_local() {
    __shared__ int s[256];
    int t = threadIdx.x;
    int i = blockIdx.x * 256 + t;
    int v = (i < NNODES) ? g_icnt[i] : 0;
    s[t] = v;
    __syncthreads();
#pragma unroll
    for (int off = 1; off < 256; off <<= 1) {
        int add = (t >= off) ? s[t - off] : 0;
        __syncthreads();
        s[t] += add;
        __syncthreads();
    }
    if (i < NNODES) g_rs[i] = s[t] - v;
    if (t == 255) g_bsum[blockIdx.x] = s[255];
}

__global__ __launch_bounds__(512) void k_scan_block() {
    __shared__ int s[512];
    int t = threadIdx.x;
    int v = (t < SCAN_BLOCKS) ? g_bsum[t] : 0;
    s[t] = v;
    __syncthreads();
#pragma unroll
    for (int off = 1; off < 512; off <<= 1) {
        int add = (t >= off) ? s[t - off] : 0;
        __syncthreads();
        s[t] += add;
        __syncthreads();
    }
    g_boff[t] = s[t] - v;
}

__global__ void k_scan_add(int E) {
    int i = blockIdx.x * 256 + threadIdx.x;
    if (i < NNODES) g_rs[i] += g_boff[blockIdx.x];
    if (i == NNODES) g_rs[NNODES] = E;
}

__global__ void k_fill(const int* __restrict__ src, const int* __restrict__ dst, int E) {
    int e = blockIdx.x * 256 + threadIdx.x;
    if (e >= E) return;
    int d = dst[e];
    int pos = g_rs[d] + atomicAdd(&g_fc[d], 1);
    g_perm[pos] = src[e];
}

// ---------------- TF32 split-MMA GEMM, pair-synchronized staging -----------
// 3xTF32 split GEMM; block 512 = 16 warps = 8 pairs. Pair (wm): 2 warps share
// a 32-row A tile (double-buffered in smem, per-pair); each warp stages HALF
// of each chunk (16 rows). Sync is a named pairwise bar.sync — no block-wide
// barrier in the mainloop. B (weights) staged once, block-resident.
// DROP >= 0 fuses BN+ReLU+threefry dropout into A staging (masks once/element).
__device__ __forceinline__ uint32_t f2tf32(float x) {
    uint32_t r;
    asm("cvt.rna.tf32.f32 %0, %1;" : "=r"(r) : "f"(x));
    return r;
}
__device__ __forceinline__ float f2tf32f(float x) {
    return __uint_as_float(f2tf32(x));
}

#define MMA_TF32(cc, a0,a1,a2,a3, b0,b1)                                       \
    asm volatile("mma.sync.aligned.m16n8k8.row.col.f32.tf32.tf32.f32 "         \
                 "{%0,%1,%2,%3}, {%4,%5,%6,%7}, {%8,%9}, {%0,%1,%2,%3};"       \
                 : "+f"(cc[0]), "+f"(cc[1]), "+f"(cc[2]), "+f"(cc[3])          \
                 : "r"(a0), "r"(a1), "r"(a2), "r"(a3), "r"(b0), "r"(b1))

template<int NCPAD, int DROP>
__global__ __launch_bounds__(512) void sgemm_tf32w(
    const float* __restrict__ A, const float* __restrict__ B,
    float* __restrict__ C, int M, int NC)
{
    constexpr int NT = NCPAD / 16;
    extern __shared__ float4 sm4[];
    float4* Bp = sm4;                          // [16*4][NCPAD+2]
    float4* Ap = sm4 + 16 * 4 * (NCPAD + 2);   // [8 pairs][2 bufs][8][34]

    int tid  = threadIdx.x;
    int warp = tid >> 5, lane = tid & 31;
    int wm = warp >> 1, wn = warp & 1;
    int gid = lane >> 2, ctid = lane & 3;
    int row0 = blockIdx.x * 256;
    int wr = wm * 32;
    int wc = wn * (NCPAD / 2);

    uint32_t kk0 = 0, kk1 = 0, kk2 = 0;
    if (DROP >= 0) {
        kk0 = g_keys[DROP * 2 + 0];
        kk1 = g_keys[DROP * 2 + 1];
        kk2 = kk0 ^ kk1 ^ 0x1BD11BDAu;
    }

    float c[2][NT][4];
#pragma unroll
    for (int mt = 0; mt < 2; mt++)
#pragma unroll
        for (int nt = 0; nt < NT; nt++)
#pragma unroll
            for (int j = 0; j < 4; j++) c[mt][nt][j] = 0.f;

    // ---- stage full B (hi/lo packed), once ----
    for (int idx = tid; idx < 64 * NCPAD; idx += 512) {
        int cc = idx & (NCPAD - 1);
        int s  = idx / NCPAD;
        int g = s >> 2, t = s & 3;
        int k = g * 8 + t;
        float a0 = (cc < NC) ? B[k * NC + cc] : 0.f;
        float a1 = (cc < NC) ? B[(k + 4) * NC + cc] : 0.f;
        float h0 = f2tf32f(a0), h1 = f2tf32f(a1);
        Bp[(g * 4 + t) * (NCPAD + 2) + cc] =
            make_float4(h0, h1, f2tf32f(a0 - h0), f2tf32f(a1 - h1));
    }

    // ---- A staging ids: each warp stages 16 rows of its pair's 32-row tile
    int srow = wn * 16 + (lane >> 1);     // local row 0..31 within pair tile
    int kg   = lane & 1;                   // k-half (0: k 0..7, 1: k 8..15)
    int gr   = row0 + wr + srow;
    const float* Arow = A + gr * 128 + kg * 8;
    float4* ApPair = Ap + wm * 544;        // 2 bufs x 8 x 34

    // transform (BN+ReLU+drop) + hi/lo split + smem store (8 ks per thread)
    auto storeA = [&](int buf, int k0c, float4 v0, float4 v1, const uint32_t* msk) {
        float vv[8] = {v0.x, v0.y, v0.z, v0.w, v1.x, v1.y, v1.z, v1.w};
        if (DROP >= 0) {
            int cb = k0c + kg * 8;
            float4 s0 = *(const float4*)(g_scale + DROP * 128 + cb);
            float4 s1 = *(const float4*)(g_scale + DROP * 128 + cb + 4);
            float4 t0 = *(const float4*)(g_shift + DROP * 128 + cb);
            float4 t1 = *(const float4*)(g_shift + DROP * 128 + cb + 4);
            float sc[8] = {s0.x, s0.y, s0.z, s0.w, s1.x, s1.y, s1.z, s1.w};
            float sh[8] = {t0.x, t0.y, t0.z, t0.w, t1.x, t1.y, t1.z, t1.w};
#pragma unroll
            for (int t = 0; t < 8; t++) {
                float r = fmaxf(fmaf(vv[t], sc[t], sh[t]), 0.f);
                vv[t] = (msk[t] & 0x80000000u) ? 0.f : r + r;
            }
        }
        float h[8], l[8];
#pragma unroll
        for (int t = 0; t < 8; t++) {
            h[t] = f2tf32f(vv[t]);
            l[t] = f2tf32f(vv[t] - h[t]);
        }
#pragma unroll
        for (int t = 0; t < 4; t++)
            ApPair[buf * 272 + (kg * 4 + t) * 34 + srow] =
                make_float4(h[t], h[t + 4], l[t], l[t + 4]);
    };

    auto calcMasks = [&](int k0c, uint32_t* msk) {
        uint32_t ibase = (uint32_t)gr * 128u + (uint32_t)(k0c + kg * 8);
#pragma unroll
        for (int t = 0; t < 8; t++)
            msk[t] = tf_bits_xor(kk0, kk1, kk2, ibase + t);
    };

    // ---- stage chunk 0 -> buf 0 ----
    {
        float4 v0 = make_float4(0.f,0.f,0.f,0.f), v1 = v0;
        if (gr < M) { v0 = *(const float4*)(Arow); v1 = *(const float4*)(Arow + 4); }
        uint32_t msk[8];
        if (DROP >= 0) calcMasks(0, msk);
        storeA(0, 0, v0, v1, msk);
    }
    __syncthreads();   // B + all pairs' chunk0 visible

    for (int it = 0; it < 8; it++) {
        int b = it & 1;
        float4 p0 = make_float4(0.f,0.f,0.f,0.f), p1 = p0;
        uint32_t msk[8];
        if (it < 7 && gr < M) {
            p0 = *(const float4*)(Arow + (it + 1) * 16);
            p1 = *(const float4*)(Arow + (it + 1) * 16 + 4);
        }
        if (DROP >= 0 && it < 7) calcMasks((it + 1) * 16, msk);

        const float4* Ab = ApPair + b * 272;
#pragma unroll
        for (int g = 0; g < 2; g++) {
            int G = it * 2 + g;
            const float4* Abase = Ab + (g * 4 + ctid) * 34;
            float4 alo0 = Abase[gid];
            float4 ahi0 = Abase[gid + 8];
            float4 alo1 = Abase[16 + gid];
            float4 ahi1 = Abase[24 + gid];
            uint32_t ah0[4] = {__float_as_uint(alo0.x), __float_as_uint(ahi0.x),
                               __float_as_uint(alo0.y), __float_as_uint(ahi0.y)};
            uint32_t al0[4] = {__float_as_uint(alo0.z), __float_as_uint(ahi0.z),
                               __float_as_uint(alo0.w), __float_as_uint(ahi0.w)};
            uint32_t ah1[4] = {__float_as_uint(alo1.x), __float_as_uint(ahi1.x),
                               __float_as_uint(alo1.y), __float_as_uint(ahi1.y)};
            uint32_t al1[4] = {__float_as_uint(alo1.z), __float_as_uint(ahi1.z),
                               __float_as_uint(alo1.w), __float_as_uint(ahi1.w)};
            const float4* Bbase = Bp + (G * 4 + ctid) * (NCPAD + 2) + wc;
#pragma unroll
            for (int nt = 0; nt < NT; nt++) {
                float4 bb = Bbase[nt * 8 + gid];
                uint32_t bh0 = __float_as_uint(bb.x), bh1 = __float_as_uint(bb.y);
                uint32_t bl0 = __float_as_uint(bb.z), bl1 = __float_as_uint(bb.w);
                MMA_TF32(c[0][nt], ah0[0], ah0[1], ah0[2], ah0[3], bh0, bh1);
                MMA_TF32(c[0][nt], al0[0], al0[1], al0[2], al0[3], bh0, bh1);
                MMA_TF32(c[0][nt], ah0[0], ah0[1], ah0[2], ah0[3], bl0, bl1);
                MMA_TF32(c[1][nt], ah1[0], ah1[1], ah1[2], ah1[3], bh0, bh1);
                MMA_TF32(c[1][nt], al1[0], al1[1], al1[2], al1[3], bh0, bh1);
                MMA_TF32(c[1][nt], ah1[0], ah1[1], ah1[2], ah1[3], bl0, bl1);
            }
        }
        if (it < 7) {
            storeA(b ^ 1, (it + 1) * 16, p0, p1, msk);
            // pairwise barrier: 2 warps (64 threads), id = wm+1
            asm volatile("bar.sync %0, 64;" :: "r"(wm + 1) : "memory");
        }
    }

#pragma unroll
    for (int mt = 0; mt < 2; mt++) {
        int r0 = row0 + wr + mt * 16 + gid;
        int r1 = r0 + 8;
#pragma unroll
        for (int nt = 0; nt < NT; nt++) {
            int ccol = wc + nt * 8 + ctid * 2;
            if (ccol < NC) {
                if (r0 < M) *(float2*)(C + r0 * NC + ccol) = make_float2(c[mt][nt][0], c[mt][nt][1]);
                if (r1 < M) *(float2*)(C + r1 * NC + ccol) = make_float2(c[mt][nt][2], c[mt][nt][3]);
            }
        }
    }
}

// ---------------- CSR SpMM (no atomics): agg = Anorm*hw + self + bias ------
__global__ __launch_bounds__(256) void spmm128(
    const float4* __restrict__ hw, float4* __restrict__ agg,
    const float* __restrict__ bias)
{
    int row = blockIdx.x * 8 + (threadIdx.x >> 5);
    if (row >= NNODES) return;
    int lane = threadIdx.x & 31;
    int beg = __ldg(&g_rs[row]);
    int end = __ldg(&g_rs[row + 1]);
    float di = g_dinv[row];
    float di2 = di * di;

    float4 self = __ldg(hw + row * 32 + lane);
    float4 b = ((const float4*)bias)[lane];
    float4 acc  = make_float4(fmaf(self.x, di2, b.x), fmaf(self.y, di2, b.y),
                              fmaf(self.z, di2, b.z), fmaf(self.w, di2, b.w));
    float4 acc2 = make_float4(0.f, 0.f, 0.f, 0.f);

    int j = beg;
    for (; j + 1 < end; j += 2) {
        int s0 = __ldg(&g_perm[j]);
        int s1 = __ldg(&g_perm[j + 1]);
        float n0 = __ldg(&g_dinv[s0]) * di;
        float n1 = __ldg(&g_dinv[s1]) * di;
        float4 v0 = __ldg(hw + s0 * 32 + lane);
        float4 v1 = __ldg(hw + s1 * 32 + lane);
        acc.x  = fmaf(v0.x, n0, acc.x);  acc.y  = fmaf(v0.y, n0, acc.y);
        acc.z  = fmaf(v0.z, n0, acc.z);  acc.w  = fmaf(v0.w, n0, acc.w);
        acc2.x = fmaf(v1.x, n1, acc2.x); acc2.y = fmaf(v1.y, n1, acc2.y);
        acc2.z = fmaf(v1.z, n1, acc2.z); acc2.w = fmaf(v1.w, n1, acc2.w);
    }
    if (j < end) {
        int s0 = __ldg(&g_perm[j]);
        float n0 = __ldg(&g_dinv[s0]) * di;
        float4 v0 = __ldg(hw + s0 * 32 + lane);
        acc.x = fmaf(v0.x, n0, acc.x); acc.y = fmaf(v0.y, n0, acc.y);
        acc.z = fmaf(v0.z, n0, acc.z); acc.w = fmaf(v0.w, n0, acc.w);
    }
    agg[row * 32 + lane] = make_float4(acc.x + acc2.x, acc.y + acc2.y,
                                       acc.z + acc2.z, acc.w + acc2.w);
}

// ---------------- fused SpMM(40) + log_softmax -----------------------------
__global__ __launch_bounds__(256) void spmm40ls(
    const float4* __restrict__ hw, float* __restrict__ out,
    const float* __restrict__ bias)
{
    int row = blockIdx.x * 8 + (threadIdx.x >> 5);
    int lane = threadIdx.x & 31;
    bool act = (lane < 10);
    int lc = act ? lane : 9;
    int beg = __ldg(&g_rs[row]);
    int end = __ldg(&g_rs[row + 1]);
    float di = g_dinv[row];
    float di2 = di * di;

    float4 self = __ldg(hw + row * 10 + lc);
    float4 b = ((const float4*)bias)[lc];
    float4 acc = make_float4(fmaf(self.x, di2, b.x), fmaf(self.y, di2, b.y),
                             fmaf(self.z, di2, b.z), fmaf(self.w, di2, b.w));
    for (int j = beg; j < end; j++) {
        int s = __ldg(&g_perm[j]);
        float n = __ldg(&g_dinv[s]) * di;
        float4 v = __ldg(hw + s * 10 + lc);
        acc.x = fmaf(v.x, n, acc.x); acc.y = fmaf(v.y, n, acc.y);
        acc.z = fmaf(v.z, n, acc.z); acc.w = fmaf(v.w, n, acc.w);
    }
    float mx = act ? fmaxf(fmaxf(acc.x, acc.y), fmaxf(acc.z, acc.w)) : -3.4e38f;
#pragma unroll
    for (int o = 16; o; o >>= 1) mx = fmaxf(mx, __shfl_xor_sync(0xffffffffu, mx, o));
    float s = act ? (expf(acc.x - mx) + expf(acc.y - mx) +
                     expf(acc.z - mx) + expf(acc.w - mx)) : 0.f;
#pragma unroll
    for (int o = 16; o; o >>= 1) s += __shfl_xor_sync(0xffffffffu, s, o);
    float l = mx + logf(s);
    if (act)
        ((float4*)out)[row * 10 + lane] =
            make_float4(acc.x - l, acc.y - l, acc.z - l, acc.w - l);
}

// ---------------- batchnorm stats + finalize -------------------------------
__global__ __launch_bounds__(256) void k_bnstats(const float* __restrict__ h,
                                                 float* __restrict__ sums) {
    __shared__ float ss[256], sq[256];
    int tid = threadIdx.x;
    int c = tid & 127;
    int half = tid >> 7;
    int rbeg = blockIdx.x * 125;        // grid = 800, covers exactly 100000
    float s = 0.f, q = 0.f;
    for (int r = rbeg + half; r < rbeg + 125; r += 2) {
        float v = h[r * 128 + c];
        s += v;
        q = fmaf(v, v, q);
    }
    ss[tid] = s; sq[tid] = q;
    __syncthreads();
    if (half == 0) {
        atomicAdd(&sums[c],       ss[tid] + ss[tid + 128]);
        atomicAdd(&sums[128 + c], sq[tid] + sq[tid + 128]);
    }
}

__global__ void k_bnfinal(const float* __restrict__ sums,
                          const float* __restrict__ gamma, const float* __restrict__ beta,
                          float* __restrict__ sc, float* __restrict__ sh) {
    int c = threadIdx.x;
    const float inv_n = 1.0f / (float)NNODES;
    float mean = sums[c] * inv_n;
    float var  = sums[128 + c] * inv_n - mean * mean;
    var = fmaxf(var, 0.f);
    float rstd = rsqrtf(var + 1e-5f);
    float a = gamma[c] * rstd;
    sc[c] = a;
    sh[c] = beta[c] - mean * a;
}

// ---------------- launch ---------------------------------------------------
extern "C" void kernel_launch(void* const* d_in, const int* in_sizes, int n_in,
                              void* d_out, int out_size) {
    const float* x   = (const float*)d_in[0];
    const int*   ei  = (const int*)  d_in[1];
    const float* W1  = (const float*)d_in[2];
    const float* b1  = (const float*)d_in[3];
    const float* g1  = (const float*)d_in[4];
    const float* be1 = (const float*)d_in[5];
    const float* W2  = (const float*)d_in[6];
    const float* b2  = (const float*)d_in[7];
    const float* g2  = (const float*)d_in[8];
    const float* be2 = (const float*)d_in[9];
    const float* W3  = (const float*)d_in[10];
    const float* b3  = (const float*)d_in[11];
    int E = in_sizes[1] / 2;
    const int* src = ei;
    const int* dst = ei + E;
    float* out = (float*)d_out;

    void *pA, *pB, *pH3, *pS, *pSc, *pSh;
    cudaGetSymbolAddress(&pA,  g_bufA);
    cudaGetSymbolAddress(&pB,  g_bufB);
    cudaGetSymbolAddress(&pH3, g_hw3);
    cudaGetSymbolAddress(&pS,  g_sums);
    cudaGetSymbolAddress(&pSc, g_scale);
    cudaGetSymbolAddress(&pSh, g_shift);
    float4* bufA = (float4*)pA;
    float4* bufB = (float4*)pB;
    float4* hw3  = (float4*)pH3;
    float* sums  = (float*)pS;
    float* scale = (float*)pSc;
    float* shift = (float*)pSh;

    const int GN     = (NNODES + 255) / 256;
    const int GE     = (E + 255) / 256;
    const int GROW   = NNODES / 8;               // 12500
    const int GM2    = (NNODES + 255) / 256;     // 391

    // smem: B = 16*4*(NCPAD+2) float4; A = 8 pairs * 2 bufs * 8 * 34 float4
    const int SM128 = (16 * 4 * 130 + 8 * 2 * 8 * 34) * (int)sizeof(float4);  // 202752
    const int SM64  = (16 * 4 * 66  + 8 * 2 * 8 * 34) * (int)sizeof(float4);  // 137216
    cudaFuncSetAttribute(sgemm_tf32w<128,-1>, cudaFuncAttributeMaxDynamicSharedMemorySize, SM128);
    cudaFuncSetAttribute(sgemm_tf32w<128, 0>, cudaFuncAttributeMaxDynamicSharedMemorySize, SM128);
    cudaFuncSetAttribute(sgemm_tf32w<64,  1>, cudaFuncAttributeMaxDynamicSharedMemorySize, SM64);

    // preprocessing (layer-1 GEMM kept at launch #4 so ncu captures it)
    k_zero  <<<GN, 256>>>();
    k_degree<<<GE, 256>>>(dst, E);
    k_keys  <<<1, 32>>>();
    sgemm_tf32w<128,-1><<<GM2, 512, SM128>>>(x, W1, (float*)bufA, NNODES, 128);
    k_dinv      <<<GN, 256>>>();
    k_scan_local<<<SCAN_BLOCKS, 256>>>();
    k_scan_block<<<1, 512>>>();
    k_scan_add  <<<SCAN_BLOCKS, 256>>>(E);
    k_fill      <<<GE, 256>>>(src, dst, E);

    // ---- layer 1: spmm -> stats -> (BN+ReLU+drop fused into GEMM2) ----
    spmm128 <<<GROW, 256>>>(bufA, bufB, b1);
    k_bnstats<<<800, 256>>>((const float*)bufB, sums);
    k_bnfinal<<<1, 128>>>(sums, g1, be1, scale, shift);

    // ---- layer 2 ----
    sgemm_tf32w<128, 0><<<GM2, 512, SM128>>>((const float*)bufB, W2, (float*)bufA, NNODES, 128);
    spmm128 <<<GROW, 256>>>(bufA, bufB, b2);
    k_bnstats<<<800, 256>>>((const float*)bufB, sums + 256);
    k_bnfinal<<<1, 128>>>(sums + 256, g2, be2, scale + 128, shift + 128);

    // ---- layer 3 (drop fused) + fused log_softmax ----
    sgemm_tf32w<64, 1><<<GM2, 512, SM64>>>((const float*)bufB, W3, (float*)hw3, NNODES, 40);
    spmm40ls<<<GROW, 256>>>(hw3, out, b3);
}

// round 13
// speedup vs baseline: 1.5471x; 1.1763x over previous
#include <cuda_runtime.h>
#include <cstdint>

#define NNODES 100000
#define MAXE   1000000

// ---------------- scratch (static __device__ globals; no allocation) -------
__device__ __align__(16) float4 g_bufA[NNODES * 32];   // 100000 x 128 floats
__device__ __align__(16) float4 g_bufB[NNODES * 32];   // 100000 x 128 floats
__device__ __align__(16) float4 g_hw3 [NNODES * 10];   // 100000 x 40 floats
__device__ float g_dinv[NNODES];
__device__ int   g_icnt[NNODES];
__device__ int   g_fc  [NNODES];
__device__ int   g_rs  [NNODES + 1];
__device__ int   g_perm[MAXE];
__device__ int   g_bsum[512];
__device__ int   g_boff[512];
__device__ float g_sums[512];
__device__ __align__(16) float g_scale[256];
__device__ __align__(16) float g_shift[256];
__device__ unsigned g_keys[4];

#define SCAN_BLOCKS 391

// ---------------- threefry2x32 (JAX-exact, 20 rounds) ----------------------
__device__ __forceinline__ void tf_round(uint32_t &x0, uint32_t &x1, int r) {
    x0 += x1;
    x1 = __funnelshift_l(x1, x1, r);
    x1 ^= x0;
}

__device__ __forceinline__ uint2 tf_full(uint32_t k0, uint32_t k1, uint32_t x0, uint32_t x1) {
    uint32_t k2 = k0 ^ k1 ^ 0x1BD11BDAu;
    x0 += k0; x1 += k1;
    tf_round(x0,x1,13); tf_round(x0,x1,15); tf_round(x0,x1,26); tf_round(x0,x1,6);
    x0 += k1; x1 += k2 + 1u;
    tf_round(x0,x1,17); tf_round(x0,x1,29); tf_round(x0,x1,16); tf_round(x0,x1,24);
    x0 += k2; x1 += k0 + 2u;
    tf_round(x0,x1,13); tf_round(x0,x1,15); tf_round(x0,x1,26); tf_round(x0,x1,6);
    x0 += k0; x1 += k1 + 3u;
    tf_round(x0,x1,17); tf_round(x0,x1,29); tf_round(x0,x1,16); tf_round(x0,x1,24);
    x0 += k1; x1 += k2 + 4u;
    tf_round(x0,x1,13); tf_round(x0,x1,15); tf_round(x0,x1,26); tf_round(x0,x1,6);
    x0 += k2; x1 += k0 + 5u;
    return make_uint2(x0, x1);
}

__device__ __forceinline__ uint32_t tf_bits_xor(uint32_t k0, uint32_t k1, uint32_t k2, uint32_t ctr) {
    uint32_t x0 = k0;
    uint32_t x1 = ctr + k1;
    tf_round(x0,x1,13); tf_round(x0,x1,15); tf_round(x0,x1,26); tf_round(x0,x1,6);
    x0 += k1; x1 += k2 + 1u;
    tf_round(x0,x1,17); tf_round(x0,x1,29); tf_round(x0,x1,16); tf_round(x0,x1,24);
    x0 += k2; x1 += k0 + 2u;
    tf_round(x0,x1,13); tf_round(x0,x1,15); tf_round(x0,x1,26); tf_round(x0,x1,6);
    x0 += k0; x1 += k1 + 3u;
    tf_round(x0,x1,17); tf_round(x0,x1,29); tf_round(x0,x1,16); tf_round(x0,x1,24);
    x0 += k1; x1 += k2 + 4u;
    tf_round(x0,x1,13); tf_round(x0,x1,15); tf_round(x0,x1,26); tf_round(x0,x1,6);
    x0 += k2; x1 += k0 + 5u;
    return x0 ^ x1;
}

__global__ void k_keys() {
    if (threadIdx.x == 0) {
        uint2 a = tf_full(0u, 42u, 0u, 0u);
        uint2 b = tf_full(0u, 42u, 0u, 1u);
        g_keys[0] = a.x; g_keys[1] = a.y;
        g_keys[2] = b.x; g_keys[3] = b.y;
    }
}

// ---------------- graph preprocessing --------------------------------------
__global__ void k_zero() {
    int i = blockIdx.x * 256 + threadIdx.x;
    if (i < NNODES) { g_icnt[i] = 0; g_fc[i] = 0; }
    if (i < 512)    g_sums[i] = 0.f;
}

__global__ void k_degree(const int* __restrict__ dst, int E) {
    int e = blockIdx.x * 256 + threadIdx.x;
    if (e < E) atomicAdd(&g_icnt[dst[e]], 1);
}

__global__ void k_dinv() {
    int i = blockIdx.x * 256 + threadIdx.x;
    if (i < NNODES) g_dinv[i] = rsqrtf((float)g_icnt[i] + 1.0f);
}

__global__ __launch_bounds__(256) void k_scan_local() {
    __shared__ int s[256];
    int t = threadIdx.x;
    int i = blockIdx.x * 256 + t;
    int v = (i < NNODES) ? g_icnt[i] : 0;
    s[t] = v;
    __syncthreads();
#pragma unroll
    for (int off = 1; off < 256; off <<= 1) {
        int add = (t >= off) ? s[t - off] : 0;
        __syncthreads();
        s[t] += add;
        __syncthreads();
    }
    if (i < NNODES) g_rs[i] = s[t] - v;
    if (t == 255) g_bsum[blockIdx.x] = s[255];
}

__global__ __launch_bounds__(512) void k_scan_block() {
    __shared__ int s[512];
    int t = threadIdx.x;
    int v = (t < SCAN_BLOCKS) ? g_bsum[t] : 0;
    s[t] = v;
    __syncthreads();
#pragma unroll
    for (int off = 1; off < 512; off <<= 1) {
        int add = (t >= off) ? s[t - off] : 0;
        __syncthreads();
        s[t] += add;
        __syncthreads();
    }
    g_boff[t] = s[t] - v;
}

__global__ void k_scan_add(int E) {
    int i = blockIdx.x * 256 + threadIdx.x;
    if (i < NNODES) g_rs[i] += g_boff[blockIdx.x];
    if (i == NNODES) g_rs[NNODES] = E;
}

__global__ void k_fill(const int* __restrict__ src, const int* __restrict__ dst, int E) {
    int e = blockIdx.x * 256 + threadIdx.x;
    if (e >= E) return;
    int d = dst[e];
    int pos = g_rs[d] + atomicAdd(&g_fc[d], 1);
    g_perm[pos] = src[e];
}

// ---------------- bf16 4-term split GEMM (m16n8k16), pair-sync staging -----
// a = ahi + alo (bf16 each, residual ~2^-18|a|); D += ahi*bhi + alo*bhi
//   + ahi*blo + alo*blo  -> 4 MMAs per 16-k per tile, fp32 accumulate.
// Block 512 = 16 warps = 8 pairs; pair owns a 32-row A tile (double-buffered,
// pairwise bar.sync). B (hi/lo packed) staged once, block-resident.
// DROP >= 0 fuses BN+ReLU+threefry dropout into A staging.
__device__ __forceinline__ uint2 bf16_split2(float e0, float e1) {
    uint32_t h;
    asm("cvt.rn.bf16x2.f32 %0, %1, %2;" : "=r"(h) : "f"(e1), "f"(e0));
    float r0 = e0 - __uint_as_float(h << 16);
    float r1 = e1 - __uint_as_float(h & 0xFFFF0000u);
    uint32_t l;
    asm("cvt.rn.bf16x2.f32 %0, %1, %2;" : "=r"(l) : "f"(r1), "f"(r0));
    return make_uint2(h, l);
}

#define MMA_BF16(cc, a0,a1,a2,a3, b0,b1)                                       \
    asm volatile("mma.sync.aligned.m16n8k16.row.col.f32.bf16.bf16.f32 "        \
                 "{%0,%1,%2,%3}, {%4,%5,%6,%7}, {%8,%9}, {%0,%1,%2,%3};"       \
                 : "+f"(cc[0]), "+f"(cc[1]), "+f"(cc[2]), "+f"(cc[3])          \
                 : "r"(a0), "r"(a1), "r"(a2), "r"(a3), "r"(b0), "r"(b1))

template<int NCPAD, int DROP>
__global__ __launch_bounds__(512) void sgemm_bf16w(
    const float* __restrict__ A, const float* __restrict__ B,
    float* __restrict__ C, int M, int NC)
{
    constexpr int NT = NCPAD / 16;
    constexpr int BSTR = NCPAD + 2;
    extern __shared__ float4 sm4[];
    float4* Bp = sm4;                          // [8 chunks][4 c][BSTR]
    float4* Ap = sm4 + 8 * 4 * BSTR;           // [8 pairs][2 bufs][4 c][34]

    int tid  = threadIdx.x;
    int warp = tid >> 5, lane = tid & 31;
    int wm = warp >> 1, wn = warp & 1;
    int gid = lane >> 2, ctid = lane & 3;
    int row0 = blockIdx.x * 256;
    int wr = wm * 32;
    int wc = wn * (NCPAD / 2);

    uint32_t kk0 = 0, kk1 = 0, kk2 = 0;
    if (DROP >= 0) {
        kk0 = g_keys[DROP * 2 + 0];
        kk1 = g_keys[DROP * 2 + 1];
        kk2 = kk0 ^ kk1 ^ 0x1BD11BDAu;
    }

    float c[2][NT][4];
#pragma unroll
    for (int mt = 0; mt < 2; mt++)
#pragma unroll
        for (int nt = 0; nt < NT; nt++)
#pragma unroll
            for (int j = 0; j < 4; j++) c[mt][nt][j] = 0.f;

    // ---- stage full B (hi/lo bf16x2 packed), once ----
    // Bp[G][c][col] = {hi(kG+2c,kG+2c+1), hi(kG+2c+8,kG+2c+9), lo.., lo..}
    for (int idx = tid; idx < 8 * 4 * NCPAD; idx += 512) {
        int cc = idx & (NCPAD - 1);
        int s  = idx / NCPAD;          // 0..31
        int G = s >> 2, cgrp = s & 3;
        int k = G * 16 + cgrp * 2;
        float v0 = (cc < NC) ? B[k * NC + cc]       : 0.f;
        float v1 = (cc < NC) ? B[(k + 1) * NC + cc] : 0.f;
        float v2 = (cc < NC) ? B[(k + 8) * NC + cc] : 0.f;
        float v3 = (cc < NC) ? B[(k + 9) * NC + cc] : 0.f;
        uint2 p0 = bf16_split2(v0, v1);
        uint2 p1 = bf16_split2(v2, v3);
        Bp[(G * 4 + cgrp) * BSTR + cc] =
            make_float4(__uint_as_float(p0.x), __uint_as_float(p1.x),
                        __uint_as_float(p0.y), __uint_as_float(p1.y));
    }

    // ---- A staging ids: 16 rows x 16 k per warp per chunk; 2 lanes/row ----
    int srow = wn * 16 + (lane >> 1);   // local row in pair tile
    int half = lane & 1;                // c-group half: cs {0,1} or {2,3}
    int gr   = row0 + wr + srow;
    const float* Arow = A + gr * 128 + half * 4;
    float4* ApPair = Ap + wm * 272;     // 2 bufs x 4 x 34

    // transform + split + store: thread covers k = k0c+half*4+{0..3, 8..11}
    auto storeA = [&](int buf, int k0c, float4 v0, float4 v1, const uint32_t* msk) {
        float vv[8] = {v0.x, v0.y, v0.z, v0.w, v1.x, v1.y, v1.z, v1.w};
        if (DROP >= 0) {
            int cb = k0c + half * 4;
            float4 s0 = *(const float4*)(g_scale + DROP * 128 + cb);
            float4 s1 = *(const float4*)(g_scale + DROP * 128 + cb + 8);
            float4 t0 = *(const float4*)(g_shift + DROP * 128 + cb);
            float4 t1 = *(const float4*)(g_shift + DROP * 128 + cb + 8);
            float sc[8] = {s0.x, s0.y, s0.z, s0.w, s1.x, s1.y, s1.z, s1.w};
            float sh[8] = {t0.x, t0.y, t0.z, t0.w, t1.x, t1.y, t1.z, t1.w};
#pragma unroll
            for (int t = 0; t < 8; t++) {
                float r = fmaxf(fmaf(vv[t], sc[t], sh[t]), 0.f);
                vv[t] = (msk[t] & 0x80000000u) ? 0.f : r + r;
            }
        }
        uint2 p0 = bf16_split2(vv[0], vv[1]);   // k 4h, 4h+1
        uint2 p1 = bf16_split2(vv[2], vv[3]);   // k 4h+2, 4h+3
        uint2 p2 = bf16_split2(vv[4], vv[5]);   // k 4h+8, 4h+9
        uint2 p3 = bf16_split2(vv[6], vv[7]);   // k 4h+10, 4h+11
        ApPair[buf * 136 + (half * 2 + 0) * 34 + srow] =
            make_float4(__uint_as_float(p0.x), __uint_as_float(p2.x),
                        __uint_as_float(p0.y), __uint_as_float(p2.y));
        ApPair[buf * 136 + (half * 2 + 1) * 34 + srow] =
            make_float4(__uint_as_float(p1.x), __uint_as_float(p3.x),
                        __uint_as_float(p1.y), __uint_as_float(p3.y));
    };

    auto calcMasks = [&](int k0c, uint32_t* msk) {
        uint32_t ibase = (uint32_t)gr * 128u + (uint32_t)(k0c + half * 4);
#pragma unroll
        for (int t = 0; t < 4; t++) {
            msk[t]     = tf_bits_xor(kk0, kk1, kk2, ibase + t);
            msk[t + 4] = tf_bits_xor(kk0, kk1, kk2, ibase + 8 + t);
        }
    };

    // ---- stage chunk 0 -> buf 0 ----
    {
        float4 v0 = make_float4(0.f,0.f,0.f,0.f), v1 = v0;
        if (gr < M) { v0 = *(const float4*)(Arow); v1 = *(const float4*)(Arow + 8); }
        uint32_t msk[8];
        if (DROP >= 0) calcMasks(0, msk);
        storeA(0, 0, v0, v1, msk);
    }
    __syncthreads();   // B + all pairs' chunk0 visible

    for (int it = 0; it < 8; it++) {
        int b = it & 1;
        float4 p0 = make_float4(0.f,0.f,0.f,0.f), p1 = p0;
        uint32_t msk[8];
        if (it < 7 && gr < M) {
            p0 = *(const float4*)(Arow + (it + 1) * 16);
            p1 = *(const float4*)(Arow + (it + 1) * 16 + 8);
        }
        if (DROP >= 0 && it < 7) calcMasks((it + 1) * 16, msk);

        const float4* Ab = ApPair + b * 136 + ctid * 34;
        uint32_t ahi[2][4], alo[2][4];
#pragma unroll
        for (int mt = 0; mt < 2; mt++) {
            float4 A0 = Ab[mt * 16 + gid];
            float4 A1 = Ab[mt * 16 + gid + 8];
            ahi[mt][0] = __float_as_uint(A0.x); ahi[mt][1] = __float_as_uint(A1.x);
            ahi[mt][2] = __float_as_uint(A0.y); ahi[mt][3] = __float_as_uint(A1.y);
            alo[mt][0] = __float_as_uint(A0.z); alo[mt][1] = __float_as_uint(A1.z);
            alo[mt][2] = __float_as_uint(A0.w); alo[mt][3] = __float_as_uint(A1.w);
        }
        const float4* Bbase = Bp + (it * 4 + ctid) * BSTR + wc;
#pragma unroll
        for (int nt = 0; nt < NT; nt++) {
            float4 bb = Bbase[nt * 8 + gid];
            uint32_t bh0 = __float_as_uint(bb.x), bh1 = __float_as_uint(bb.y);
            uint32_t bl0 = __float_as_uint(bb.z), bl1 = __float_as_uint(bb.w);
#pragma unroll
            for (int mt = 0; mt < 2; mt++) {
                MMA_BF16(c[mt][nt], ahi[mt][0], ahi[mt][1], ahi[mt][2], ahi[mt][3], bh0, bh1);
                MMA_BF16(c[mt][nt], alo[mt][0], alo[mt][1], alo[mt][2], alo[mt][3], bh0, bh1);
                MMA_BF16(c[mt][nt], ahi[mt][0], ahi[mt][1], ahi[mt][2], ahi[mt][3], bl0, bl1);
                MMA_BF16(c[mt][nt], alo[mt][0], alo[mt][1], alo[mt][2], alo[mt][3], bl0, bl1);
            }
        }
        if (it < 7) {
            storeA(b ^ 1, (it + 1) * 16, p0, p1, msk);
            asm volatile("bar.sync %0, 64;" :: "r"(wm + 1) : "memory");
        }
    }

#pragma unroll
    for (int mt = 0; mt < 2; mt++) {
        int r0 = row0 + wr + mt * 16 + gid;
        int r1 = r0 + 8;
#pragma unroll
        for (int nt = 0; nt < NT; nt++) {
            int ccol = wc + nt * 8 + ctid * 2;
            if (ccol < NC) {
                if (r0 < M) *(float2*)(C + r0 * NC + ccol) = make_float2(c[mt][nt][0], c[mt][nt][1]);
                if (r1 < M) *(float2*)(C + r1 * NC + ccol) = make_float2(c[mt][nt][2], c[mt][nt][3]);
            }
        }
    }
}

// ---------------- CSR SpMM (no atomics): agg = Anorm*hw + self + bias ------
__global__ __launch_bounds__(256) void spmm128(
    const float4* __restrict__ hw, float4* __restrict__ agg,
    const float* __restrict__ bias)
{
    int row = blockIdx.x * 8 + (threadIdx.x >> 5);
    if (row >= NNODES) return;
    int lane = threadIdx.x & 31;
    int beg = __ldg(&g_rs[row]);
    int end = __ldg(&g_rs[row + 1]);
    float di = g_dinv[row];
    float di2 = di * di;

    float4 self = __ldg(hw + row * 32 + lane);
    float4 b = ((const float4*)bias)[lane];
    float4 acc  = make_float4(fmaf(self.x, di2, b.x), fmaf(self.y, di2, b.y),
                              fmaf(self.z, di2, b.z), fmaf(self.w, di2, b.w));
    float4 acc2 = make_float4(0.f, 0.f, 0.f, 0.f);

    int j = beg;
    for (; j + 1 < end; j += 2) {
        int s0 = __ldg(&g_perm[j]);
        int s1 = __ldg(&g_perm[j + 1]);
        float n0 = __ldg(&g_dinv[s0]) * di;
        float n1 = __ldg(&g_dinv[s1]) * di;
        float4 v0 = __ldg(hw + s0 * 32 + lane);
        float4 v1 = __ldg(hw + s1 * 32 + lane);
        acc.x  = fmaf(v0.x, n0, acc.x);  acc.y  = fmaf(v0.y, n0, acc.y);
        acc.z  = fmaf(v0.z, n0, acc.z);  acc.w  = fmaf(v0.w, n0, acc.w);
        acc2.x = fmaf(v1.x, n1, acc2.x); acc2.y = fmaf(v1.y, n1, acc2.y);
        acc2.z = fmaf(v1.z, n1, acc2.z); acc2.w = fmaf(v1.w, n1, acc2.w);
    }
    if (j < end) {
        int s0 = __ldg(&g_perm[j]);
        float n0 = __ldg(&g_dinv[s0]) * di;
        float4 v0 = __ldg(hw + s0 * 32 + lane);
        acc.x = fmaf(v0.x, n0, acc.x); acc.y = fmaf(v0.y, n0, acc.y);
        acc.z = fmaf(v0.z, n0, acc.z); acc.w = fmaf(v0.w, n0, acc.w);
    }
    agg[row * 32 + lane] = make_float4(acc.x + acc2.x, acc.y + acc2.y,
                                       acc.z + acc2.z, acc.w + acc2.w);
}

// ---------------- fused SpMM(40) + log_softmax -----------------------------
__global__ __launch_bounds__(256) void spmm40ls(
    const float4* __restrict__ hw, float* __restrict__ out,
    const float* __restrict__ bias)
{
    int row = blockIdx.x * 8 + (threadIdx.x >> 5);
    int lane = threadIdx.x & 31;
    bool act = (lane < 10);
    int lc = act ? lane : 9;
    int beg = __ldg(&g_rs[row]);
    int end = __ldg(&g_rs[row + 1]);
    float di = g_dinv[row];
    float di2 = di * di;

    float4 self = __ldg(hw + row * 10 + lc);
    float4 b = ((const float4*)bias)[lc];
    float4 acc = make_float4(fmaf(self.x, di2, b.x), fmaf(self.y, di2, b.y),
                             fmaf(self.z, di2, b.z), fmaf(self.w, di2, b.w));
    for (int j = beg; j < end; j++) {
        int s = __ldg(&g_perm[j]);
        float n = __ldg(&g_dinv[s]) * di;
        float4 v = __ldg(hw + s * 10 + lc);
        acc.x = fmaf(v.x, n, acc.x); acc.y = fmaf(v.y, n, acc.y);
        acc.z = fmaf(v.z, n, acc.z); acc.w = fmaf(v.w, n, acc.w);
    }
    float mx = act ? fmaxf(fmaxf(acc.x, acc.y), fmaxf(acc.z, acc.w)) : -3.4e38f;
#pragma unroll
    for (int o = 16; o; o >>= 1) mx = fmaxf(mx, __shfl_xor_sync(0xffffffffu, mx, o));
    float s = act ? (expf(acc.x - mx) + expf(acc.y - mx) +
                     expf(acc.z - mx) + expf(acc.w - mx)) : 0.f;
#pragma unroll
    for (int o = 16; o; o >>= 1) s += __shfl_xor_sync(0xffffffffu, s, o);
    float l = mx + logf(s);
    if (act)
        ((float4*)out)[row * 10 + lane] =
            make_float4(acc.x - l, acc.y - l, acc.z - l, acc.w - l);
}

// ---------------- batchnorm stats + finalize -------------------------------
__global__ __launch_bounds__(256) void k_bnstats(const float* __restrict__ h,
                                                 float* __restrict__ sums) {
    __shared__ float ss[256], sq[256];
    int tid = threadIdx.x;
    int c = tid & 127;
    int half = tid >> 7;
    int rbeg = blockIdx.x * 125;        // grid = 800, covers exactly 100000
    float s = 0.f, q = 0.f;
    for (int r = rbeg + half; r < rbeg + 125; r += 2) {
        float v = h[r * 128 + c];
        s += v;
        q = fmaf(v, v, q);
    }
    ss[tid] = s; sq[tid] = q;
    __syncthreads();
    if (half == 0) {
        atomicAdd(&sums[c],       ss[tid] + ss[tid + 128]);
        atomicAdd(&sums[128 + c], sq[tid] + sq[tid + 128]);
    }
}

__global__ void k_bnfinal(const float* __restrict__ sums,
                          const float* __restrict__ gamma, const float* __restrict__ beta,
                          float* __restrict__ sc, float* __restrict__ sh) {
    int c = threadIdx.x;
    const float inv_n = 1.0f / (float)NNODES;
    float mean = sums[c] * inv_n;
    float var  = sums[128 + c] * inv_n - mean * mean;
    var = fmaxf(var, 0.f);
    float rstd = rsqrtf(var + 1e-5f);
    float a = gamma[c] * rstd;
    sc[c] = a;
    sh[c] = beta[c] - mean * a;
}

// ---------------- launch ---------------------------------------------------
extern "C" void kernel_launch(void* const* d_in, const int* in_sizes, int n_in,
                              void* d_out, int out_size) {
    const float* x   = (const float*)d_in[0];
    const int*   ei  = (const int*)  d_in[1];
    const float* W1  = (const float*)d_in[2];
    const float* b1  = (const float*)d_in[3];
    const float* g1  = (const float*)d_in[4];
    const float* be1 = (const float*)d_in[5];
    const float* W2  = (const float*)d_in[6];
    const float* b2  = (const float*)d_in[7];
    const float* g2  = (const float*)d_in[8];
    const float* be2 = (const float*)d_in[9];
    const float* W3  = (const float*)d_in[10];
    const float* b3  = (const float*)d_in[11];
    int E = in_sizes[1] / 2;
    const int* src = ei;
    const int* dst = ei + E;
    float* out = (float*)d_out;

    void *pA, *pB, *pH3, *pS, *pSc, *pSh;
    cudaGetSymbolAddress(&pA,  g_bufA);
    cudaGetSymbolAddress(&pB,  g_bufB);
    cudaGetSymbolAddress(&pH3, g_hw3);
    cudaGetSymbolAddress(&pS,  g_sums);
    cudaGetSymbolAddress(&pSc, g_scale);
    cudaGetSymbolAddress(&pSh, g_shift);
    float4* bufA = (float4*)pA;
    float4* bufB = (float4*)pB;
    float4* hw3  = (float4*)pH3;
    float* sums  = (float*)pS;
    float* scale = (float*)pSc;
    float* shift = (float*)pSh;

    const int GN     = (NNODES + 255) / 256;
    const int GE     = (E + 255) / 256;
    const int GROW   = NNODES / 8;               // 12500
    const int GM2    = (NNODES + 255) / 256;     // 391

    // smem: B = 8*4*(NCPAD+2) f4; A = 8 pairs * 2 bufs * 4 * 34 f4
    const int SM128 = (8 * 4 * 130 + 8 * 2 * 4 * 34) * (int)sizeof(float4);  // 101376
    const int SM64  = (8 * 4 * 66  + 8 * 2 * 4 * 34) * (int)sizeof(float4);  // 68608
    cudaFuncSetAttribute(sgemm_bf16w<128,-1>, cudaFuncAttributeMaxDynamicSharedMemorySize, SM128);
    cudaFuncSetAttribute(sgemm_bf16w<128, 0>, cudaFuncAttributeMaxDynamicSharedMemorySize, SM128);
    cudaFuncSetAttribute(sgemm_bf16w<64,  1>, cudaFuncAttributeMaxDynamicSharedMemorySize, SM64);

    // preprocessing (layer-1 GEMM kept at launch #4 so ncu captures it)
    k_zero  <<<GN, 256>>>();
    k_degree<<<GE, 256>>>(dst, E);
    k_keys  <<<1, 32>>>();
    sgemm_bf16w<128,-1><<<GM2, 512, SM128>>>(x, W1, (float*)bufA, NNODES, 128);
    k_dinv      <<<GN, 256>>>();
    k_scan_local<<<SCAN_BLOCKS, 256>>>();
    k_scan_block<<<1, 512>>>();
    k_scan_add  <<<SCAN_BLOCKS, 256>>>(E);
    k_fill      <<<GE, 256>>>(src, dst, E);

    // ---- layer 1: spmm -> stats -> (BN+ReLU+drop fused into GEMM2) ----
    spmm128 <<<GROW, 256>>>(bufA, bufB, b1);
    k_bnstats<<<800, 256>>>((const float*)bufB, sums);
    k_bnfinal<<<1, 128>>>(sums, g1, be1, scale, shift);

    // ---- layer 2 ----
    sgemm_bf16w<128, 0><<<GM2, 512, SM128>>>((const float*)bufB, W2, (float*)bufA, NNODES, 128);
    spmm128 <<<GROW, 256>>>(bufA, bufB, b2);
    k_bnstats<<<800, 256>>>((const float*)bufB, sums + 256);
    k_bnfinal<<<1, 128>>>(sums + 256, g2, be2, scale + 128, shift + 128);

    // ---- layer 3 (drop fused) + fused log_softmax ----
    sgemm_bf16w<64, 1><<<GM2, 512, SM64>>>((const float*)bufB, W3, (float*)hw3, NNODES, 40);
    spmm40ls<<<GROW, 256>>>(hw3, out, b3);
}